// round 3
// baseline (speedup 1.0000x reference)
#include <cuda_runtime.h>
#include <math.h>

#define NN 20000
#define EE 640000
#define DIN 256
#define HID 128
#define HEADSN 4
#define DOUT 128
#define RR 32
#define E2 (EE + NN)
#define W1COLS (HEADSN * HID)   // 512

// ---------------- scratch (device globals; no allocation allowed) -------------
__device__ __align__(256) float d_counts[NN * RR];            // per-(src,rel) counts
__device__ __align__(256) int   d_deg[NN];
__device__ __align__(256) int   d_offsets[NN + 1];
__device__ __align__(256) int   d_cursor[NN];
__device__ __align__(256) int   d_csr_src[E2];
__device__ __align__(256) float d_RW1[RR * W1COLS];           // rel_emb @ W1
__device__ __align__(256) float d_h1[(size_t)NN * W1COLS];    // x_mod @ W1
__device__ __align__(256) float d_as1[NN * HEADSN];
__device__ __align__(256) float d_ad1[NN * HEADSN];
__device__ __align__(256) float d_agg1[(size_t)NN * W1COLS];  // elu(gat1 + b1)
__device__ __align__(256) float d_h2[(size_t)NN * DOUT];      // agg1 @ W2
__device__ __align__(256) float d_as2[NN];
__device__ __align__(256) float d_ad2[NN];

// ---------------- init ----------------
__global__ void k_init() {
    int i = blockIdx.x * blockDim.x + threadIdx.x;
    if (i < NN * RR) d_counts[i] = 0.f;
    if (i < NN) { d_deg[i] = 1; d_cursor[i] = 0; }   // deg starts at 1 for self loop
}

// ---------------- histogram: counts[src,rel]++, deg[dst]++ ----------------
__global__ void k_hist(const int* __restrict__ ei, const int* __restrict__ et) {
    int e = blockIdx.x * blockDim.x + threadIdx.x;
    if (e < EE) {
        int s = ei[e];
        int d = ei[EE + e];
        int r = et[e];
        atomicAdd(&d_counts[s * RR + r], 1.0f);
        atomicAdd(&d_deg[d], 1);
    }
}

// ---------------- exclusive scan over deg -> offsets (single block) ----------
__global__ void k_scan() {
    __shared__ int sh[1024];
    int t = threadIdx.x;
    int carry = 0;
    for (int base = 0; base < NN; base += 1024) {
        int i = base + t;
        int v = (i < NN) ? d_deg[i] : 0;
        sh[t] = v;
        __syncthreads();
        for (int off = 1; off < 1024; off <<= 1) {
            int u = (t >= off) ? sh[t - off] : 0;
            __syncthreads();
            sh[t] += u;
            __syncthreads();
        }
        if (i < NN) d_offsets[i] = carry + sh[t] - v;   // exclusive
        int tot = sh[1023];
        __syncthreads();
        carry += tot;
    }
    if (t == 0) d_offsets[NN] = carry;
}

// ---------------- CSR fill (edges + self loops) ----------------
__global__ void k_fill(const int* __restrict__ ei) {
    int e = blockIdx.x * blockDim.x + threadIdx.x;
    if (e < EE) {
        int s = ei[e];
        int d = ei[EE + e];
        int pos = d_offsets[d] + atomicAdd(&d_cursor[d], 1);
        d_csr_src[pos] = s;
    } else if (e < E2) {
        int n = e - EE;
        int pos = d_offsets[n] + atomicAdd(&d_cursor[n], 1);
        d_csr_src[pos] = n;
    }
}

// ---------------- RW1 = rel_emb @ W1  (32 x 512, K=256) ----------------
__global__ void k_rw1(const float* __restrict__ rel, const float* __restrict__ W1) {
    int r = blockIdx.x;
    int j = threadIdx.x;   // 512
    float acc = 0.f;
    const float* rr = rel + r * DIN;
    for (int k = 0; k < DIN; k++)
        acc = fmaf(rr[k], W1[(size_t)k * W1COLS + j], acc);
    d_RW1[r * W1COLS + j] = acc;
}

// ---------------- tiled SIMT fp32 GEMM, scratch buffers selected at compile time
// MODE 0: d_h1 = Aext(x) @ Bext(W1)  +  d_counts @ d_RW1   (M=NN, N=512, K=256, K2=32)
// MODE 1: d_h2 = d_agg1 @ Bext(W2)                         (M=NN, N=128, K=512)
// 64x64 tile, BK=16, 256 threads, 4x4 micro-tile per thread.
template <int MODE>
__global__ __launch_bounds__(256) void k_gemm(const float* __restrict__ Aext,
                                              const float* __restrict__ Bext)
{
    constexpr int M = NN;
    constexpr int N = (MODE == 0) ? W1COLS : DOUT;
    constexpr int NPASS = (MODE == 0) ? 2 : 1;

    __shared__ float As[64][17];
    __shared__ float Bs[16][64];

    int tid = threadIdx.x;
    int ty = tid / 16, tx = tid % 16;
    int rowBase = blockIdx.y * 64;
    int colBase = blockIdx.x * 64;

    int la_r = tid / 4;          // 0..63
    int la_c = (tid % 4) * 4;    // 0,4,8,12
    int lb_r = tid / 16;         // 0..15
    int lb_c = (tid % 16) * 4;   // 0..60

    float acc[4][4];
#pragma unroll
    for (int i = 0; i < 4; i++)
#pragma unroll
        for (int j = 0; j < 4; j++) acc[i][j] = 0.f;

#pragma unroll
    for (int pass = 0; pass < NPASS; pass++) {
        const float* Ap;
        const float* Bp;
        int Kp;
        if (MODE == 0) {
            if (pass == 0) { Ap = Aext; Bp = Bext; Kp = DIN; }
            else           { Ap = d_counts; Bp = d_RW1; Kp = RR; }
        } else {
            Ap = d_agg1; Bp = Bext; Kp = W1COLS;
        }

        for (int k0 = 0; k0 < Kp; k0 += 16) {
            int gr = rowBase + la_r;
            float4 av = make_float4(0.f, 0.f, 0.f, 0.f);
            if (gr < M) av = *(const float4*)&Ap[(size_t)gr * Kp + k0 + la_c];
            As[la_r][la_c + 0] = av.x;
            As[la_r][la_c + 1] = av.y;
            As[la_r][la_c + 2] = av.z;
            As[la_r][la_c + 3] = av.w;

            float4 bv = *(const float4*)&Bp[(size_t)(k0 + lb_r) * N + colBase + lb_c];
            *(float4*)&Bs[lb_r][lb_c] = bv;
            __syncthreads();

#pragma unroll
            for (int k = 0; k < 16; k++) {
                float ra[4], rb[4];
#pragma unroll
                for (int i = 0; i < 4; i++) ra[i] = As[ty * 4 + i][k];
#pragma unroll
                for (int j = 0; j < 4; j++) rb[j] = Bs[k][tx * 4 + j];
#pragma unroll
                for (int i = 0; i < 4; i++)
#pragma unroll
                    for (int j = 0; j < 4; j++)
                        acc[i][j] = fmaf(ra[i], rb[j], acc[i][j]);
            }
            __syncthreads();
        }
    }

    float* C = (MODE == 0) ? d_h1 : d_h2;
#pragma unroll
    for (int i = 0; i < 4; i++) {
        int gr = rowBase + ty * 4 + i;
        if (gr < M) {
            float4 v = make_float4(acc[i][0], acc[i][1], acc[i][2], acc[i][3]);
            *(float4*)&C[(size_t)gr * N + colBase + tx * 4] = v;
        }
    }
}

// ---------------- attention dot products layer 1 ----------------
__global__ void k_attn1(const float* __restrict__ att_s, const float* __restrict__ att_d) {
    int n = blockIdx.x;
    int w = threadIdx.x / 32, l = threadIdx.x % 32;
    const float* hp = &d_h1[(size_t)n * W1COLS + w * HID];
    float ss = 0.f, dd = 0.f;
#pragma unroll
    for (int i = 0; i < 4; i++) {
        float v = hp[l + i * 32];
        ss = fmaf(v, att_s[w * HID + l + i * 32], ss);
        dd = fmaf(v, att_d[w * HID + l + i * 32], dd);
    }
#pragma unroll
    for (int off = 16; off; off >>= 1) {
        ss += __shfl_down_sync(0xffffffffu, ss, off);
        dd += __shfl_down_sync(0xffffffffu, dd, off);
    }
    if (l == 0) { d_as1[n * HEADSN + w] = ss; d_ad1[n * HEADSN + w] = dd; }
}

// ---------------- attention dot products layer 2 ----------------
__global__ void k_attn2(const float* __restrict__ att_s, const float* __restrict__ att_d) {
    int n = blockIdx.x;
    int l = threadIdx.x;   // 32
    const float* hp = &d_h2[(size_t)n * DOUT];
    float ss = 0.f, dd = 0.f;
#pragma unroll
    for (int i = 0; i < 4; i++) {
        float v = hp[l + i * 32];
        ss = fmaf(v, att_s[l + i * 32], ss);
        dd = fmaf(v, att_d[l + i * 32], dd);
    }
#pragma unroll
    for (int off = 16; off; off >>= 1) {
        ss += __shfl_down_sync(0xffffffffu, ss, off);
        dd += __shfl_down_sync(0xffffffffu, dd, off);
    }
    if (l == 0) { d_as2[n] = ss; d_ad2[n] = dd; }
}

// ---------------- per-dst-node softmax aggregation ----------------
// One CTA (128 threads) per dst node. Pass 1: per-head max. Pass 2: exp /
// denominator + weighted gather-accumulate of source feature rows.
// LAYER 0: H=4, h=d_h1, out=d_agg1 (applies elu). LAYER 1: H=1, h=d_h2, out=param.
template <int LAYER>
__global__ __launch_bounds__(128) void k_agg(const float* __restrict__ bias,
                                             float* __restrict__ outp)
{
    constexpr int H = (LAYER == 0) ? HEADSN : 1;
    constexpr int C = 128;
    const float* h    = (LAYER == 0) ? d_h1 : d_h2;
    const float* asv  = (LAYER == 0) ? d_as1 : d_as2;
    const float* advv = (LAYER == 0) ? d_ad1 : d_ad2;
    float* out        = (LAYER == 0) ? d_agg1 : outp;

    int n = blockIdx.x;
    int t = threadIdx.x;
    int beg = d_offsets[n], end = d_offsets[n + 1];

    float adv[H];
#pragma unroll
    for (int hh = 0; hh < H; hh++) adv[hh] = advv[n * H + hh];

    float m[H];
#pragma unroll
    for (int hh = 0; hh < H; hh++) m[hh] = -1e30f;

    for (int e = beg; e < end; e++) {
        int s = d_csr_src[e];
#pragma unroll
        for (int hh = 0; hh < H; hh++) {
            float ev = asv[s * H + hh] + adv[hh];
            ev = ev > 0.f ? ev : 0.2f * ev;
            m[hh] = fmaxf(m[hh], ev);
        }
    }

    float denom[H], acc[H];
#pragma unroll
    for (int hh = 0; hh < H; hh++) { denom[hh] = 0.f; acc[hh] = 0.f; }

    for (int e = beg; e < end; e++) {
        int s = d_csr_src[e];
        const float* hr = &h[(size_t)s * (H * C)];
#pragma unroll
        for (int hh = 0; hh < H; hh++) {
            float ev = asv[s * H + hh] + adv[hh];
            ev = ev > 0.f ? ev : 0.2f * ev;
            float p = __expf(ev - m[hh]);
            denom[hh] += p;
            acc[hh] = fmaf(p, hr[hh * C + t], acc[hh]);
        }
    }

#pragma unroll
    for (int hh = 0; hh < H; hh++) {
        float v = acc[hh] / (denom[hh] + 1e-16f) + bias[hh * C + t];
        if (LAYER == 0) v = v > 0.f ? v : expm1f(v);
        out[(size_t)n * (H * C) + hh * C + t] = v;
    }
}

// ---------------- host side: launches only, no other CUDA API calls ----------
extern "C" void kernel_launch(void* const* d_in, const int* in_sizes, int n_in,
                              void* d_out, int out_size) {
    const float* x    = (const float*)d_in[0];
    const int*   ei   = (const int*)d_in[1];   // int32: jax silently downcasts int64
    const int*   et   = (const int*)d_in[2];
    const float* rel  = (const float*)d_in[3];
    const float* W1   = (const float*)d_in[4];
    const float* as1w = (const float*)d_in[5];
    const float* ad1w = (const float*)d_in[6];
    const float* b1   = (const float*)d_in[7];
    const float* W2   = (const float*)d_in[8];
    const float* as2w = (const float*)d_in[9];
    const float* ad2w = (const float*)d_in[10];
    const float* b2   = (const float*)d_in[11];
    float*       out  = (float*)d_out;

    // graph build
    k_init<<<(NN * RR + 255) / 256, 256>>>();
    k_hist<<<(EE + 255) / 256, 256>>>(ei, et);
    k_scan<<<1, 1024>>>();
    k_fill<<<(E2 + 255) / 256, 256>>>(ei);

    // relational projection
    k_rw1<<<RR, W1COLS>>>(rel, W1);

    // layer 1: d_h1 = x@W1 + counts@RW1
    {
        dim3 grid(W1COLS / 64, (NN + 63) / 64);
        k_gemm<0><<<grid, 256>>>(x, W1);
    }
    k_attn1<<<NN, 128>>>(as1w, ad1w);
    k_agg<0><<<NN, 128>>>(b1, nullptr);

    // layer 2: d_h2 = d_agg1@W2
    {
        dim3 grid(DOUT / 64, (NN + 63) / 64);
        k_gemm<1><<<grid, 256>>>(nullptr, W2);
    }
    k_attn2<<<NN, 32>>>(as2w, ad2w);
    k_agg<1><<<NN, 128>>>(b2, out);
}

// round 4
// speedup vs baseline: 1.5042x; 1.5042x over previous
#include <cuda_runtime.h>
#include <math.h>
#include <stdint.h>

#define NN 20000
#define EE 640000
#define DIN 256
#define HID 128
#define HEADSN 4
#define DOUT 128
#define RR 32
#define E2 (EE + NN)
#define W1COLS (HEADSN * HID)   // 512

// ---------------- scratch (device globals; no allocation allowed) -------------
__device__ __align__(256) float d_counts[NN * RR];
__device__ __align__(256) int   d_deg[NN];
__device__ __align__(256) int   d_offsets[NN + 1];
__device__ __align__(256) int   d_cursor[NN];
__device__ __align__(256) int   d_csr_src[E2];
__device__ __align__(256) float d_RW1[RR * W1COLS];
__device__ __align__(256) float d_h1[(size_t)NN * W1COLS];
__device__ __align__(256) float d_as1[NN * HEADSN];
__device__ __align__(256) float d_ad1[NN * HEADSN];
__device__ __align__(256) float d_agg1[(size_t)NN * W1COLS];
__device__ __align__(256) float d_h2[(size_t)NN * DOUT];
__device__ __align__(256) float d_as2[NN];
__device__ __align__(256) float d_ad2[NN];

__device__ __forceinline__ float to_tf32(float x) {
    uint32_t r;
    asm("cvt.rna.tf32.f32 %0, %1;" : "=r"(r) : "f"(x));
    return __uint_as_float(r);
}

// ---------------- init ----------------
__global__ void k_init() {
    int i = blockIdx.x * blockDim.x + threadIdx.x;
    if (i < NN * RR) d_counts[i] = 0.f;
    if (i < NN) { d_deg[i] = 1; d_cursor[i] = 0; }   // self loop
}

// ---------------- histogram ----------------
__global__ void k_hist(const int* __restrict__ ei, const int* __restrict__ et) {
    int e = blockIdx.x * blockDim.x + threadIdx.x;
    if (e < EE) {
        int s = ei[e];
        int d = ei[EE + e];
        int r = et[e];
        atomicAdd(&d_counts[s * RR + r], 1.0f);
        atomicAdd(&d_deg[d], 1);
    }
}

// ---------------- exclusive scan (single block, shuffle-based) ----------------
__global__ __launch_bounds__(1024) void k_scan() {
    const int PER = 20;                       // 1024*20 = 20480 >= NN
    int t = threadIdx.x;
    int lane = t & 31, w = t >> 5;
    int base = t * PER;

    int loc[PER];
    int sum = 0;
#pragma unroll
    for (int i = 0; i < PER; i++) {
        int idx = base + i;
        int v = (idx < NN) ? d_deg[idx] : 0;
        loc[i] = sum;                         // exclusive within thread
        sum += v;
    }
    // inclusive warp scan of sums
    int incl = sum;
#pragma unroll
    for (int off = 1; off < 32; off <<= 1) {
        int u = __shfl_up_sync(0xffffffffu, incl, off);
        if (lane >= off) incl += u;
    }
    __shared__ int wincl[32];
    if (lane == 31) wincl[w] = incl;
    __syncthreads();
    if (w == 0) {
        int v = wincl[lane];
        int wi = v;
#pragma unroll
        for (int off = 1; off < 32; off <<= 1) {
            int u = __shfl_up_sync(0xffffffffu, wi, off);
            if (lane >= off) wi += u;
        }
        wincl[lane] = wi;                     // inclusive over warps
    }
    __syncthreads();
    int warp_excl = (w == 0) ? 0 : wincl[w - 1];
    int thread_excl = warp_excl + (incl - sum);
#pragma unroll
    for (int i = 0; i < PER; i++) {
        int idx = base + i;
        if (idx < NN) d_offsets[idx] = thread_excl + loc[i];
    }
    if (t == 0) d_offsets[NN] = wincl[31];
}

// ---------------- CSR fill ----------------
__global__ void k_fill(const int* __restrict__ ei) {
    int e = blockIdx.x * blockDim.x + threadIdx.x;
    if (e < EE) {
        int s = ei[e];
        int d = ei[EE + e];
        int pos = d_offsets[d] + atomicAdd(&d_cursor[d], 1);
        d_csr_src[pos] = s;
    } else if (e < E2) {
        int n = e - EE;
        int pos = d_offsets[n] + atomicAdd(&d_cursor[n], 1);
        d_csr_src[pos] = n;
    }
}

// ---------------- RW1 = rel_emb @ W1 ----------------
__global__ void k_rw1(const float* __restrict__ rel, const float* __restrict__ W1) {
    int r = blockIdx.x;
    int j = threadIdx.x;
    float acc = 0.f;
    const float* rr = rel + r * DIN;
    for (int k = 0; k < DIN; k++)
        acc = fmaf(rr[k], W1[(size_t)k * W1COLS + j], acc);
    d_RW1[r * W1COLS + j] = acc;
}

// ---------------- TF32 tensor-core GEMM --------------------------------------
// MODE 0: d_h1 = x@W1 + counts@RW1   (M=NN, N=512, K=256 then K2=32)
// MODE 1: d_h2 = d_agg1 @ W2         (M=NN, N=128, K=512)
// CTA tile 128x64, BK=16, 256 threads (8 warps, 32x32 warp tiles),
// mma.sync.m16n8k8.tf32.
template <int MODE>
__global__ __launch_bounds__(256) void k_gemm_tc(const float* __restrict__ A0,
                                                 const float* __restrict__ B0)
{
    constexpr int M = NN;
    constexpr int N = (MODE == 0) ? W1COLS : DOUT;
    constexpr int NPASS = (MODE == 0) ? 2 : 1;
    constexpr int BM = 128, BK = 16;

    __shared__ float As[BM][BK + 1];      // stride 17
    __shared__ float Bs[BK][64 + 4];      // stride 68

    int tid = threadIdx.x;
    int lane = tid & 31, wid = tid >> 5;
    int wm = (wid & 3) * 32;              // warp row offset in tile
    int wn = (wid >> 2) * 32;             // warp col offset in tile
    int g = lane >> 2, tig = lane & 3;

    int rowBase = blockIdx.y * BM;
    int colBase = blockIdx.x * 64;

    int la_r = tid >> 1;                  // 0..127
    int la_c = (tid & 1) * 8;             // 0 or 8
    int lb_r = tid >> 4;                  // 0..15
    int lb_c = (tid & 15) * 4;            // 0..60

    float acc[2][4][4];
#pragma unroll
    for (int mi = 0; mi < 2; mi++)
#pragma unroll
        for (int nj = 0; nj < 4; nj++)
#pragma unroll
            for (int q = 0; q < 4; q++) acc[mi][nj][q] = 0.f;

#pragma unroll
    for (int pass = 0; pass < NPASS; pass++) {
        const float* Ap;
        const float* Bp;
        int Kp;
        if (MODE == 0) {
            if (pass == 0) { Ap = A0; Bp = B0; Kp = DIN; }
            else           { Ap = d_counts; Bp = d_RW1; Kp = RR; }
        } else {
            Ap = d_agg1; Bp = B0; Kp = W1COLS;
        }

        for (int k0 = 0; k0 < Kp; k0 += BK) {
            // load A tile (2 float4 per thread), convert to tf32
            {
                int gr = rowBase + la_r;
                float4 v0 = make_float4(0.f, 0.f, 0.f, 0.f);
                float4 v1 = make_float4(0.f, 0.f, 0.f, 0.f);
                if (gr < M) {
                    const float* ap = &Ap[(size_t)gr * Kp + k0 + la_c];
                    v0 = *(const float4*)ap;
                    v1 = *(const float4*)(ap + 4);
                }
                As[la_r][la_c + 0] = to_tf32(v0.x);
                As[la_r][la_c + 1] = to_tf32(v0.y);
                As[la_r][la_c + 2] = to_tf32(v0.z);
                As[la_r][la_c + 3] = to_tf32(v0.w);
                As[la_r][la_c + 4] = to_tf32(v1.x);
                As[la_r][la_c + 5] = to_tf32(v1.y);
                As[la_r][la_c + 6] = to_tf32(v1.z);
                As[la_r][la_c + 7] = to_tf32(v1.w);
            }
            // load B tile (1 float4 per thread)
            {
                float4 v = *(const float4*)&Bp[(size_t)(k0 + lb_r) * N + colBase + lb_c];
                Bs[lb_r][lb_c + 0] = to_tf32(v.x);
                Bs[lb_r][lb_c + 1] = to_tf32(v.y);
                Bs[lb_r][lb_c + 2] = to_tf32(v.z);
                Bs[lb_r][lb_c + 3] = to_tf32(v.w);
            }
            __syncthreads();

#pragma unroll
            for (int kk = 0; kk < BK; kk += 8) {
                uint32_t a[2][4];
#pragma unroll
                for (int mi = 0; mi < 2; mi++) {
                    int r0 = wm + mi * 16 + g;
                    a[mi][0] = __float_as_uint(As[r0][kk + tig]);
                    a[mi][1] = __float_as_uint(As[r0 + 8][kk + tig]);
                    a[mi][2] = __float_as_uint(As[r0][kk + tig + 4]);
                    a[mi][3] = __float_as_uint(As[r0 + 8][kk + tig + 4]);
                }
                uint32_t b[4][2];
#pragma unroll
                for (int nj = 0; nj < 4; nj++) {
                    int c0 = wn + nj * 8 + g;
                    b[nj][0] = __float_as_uint(Bs[kk + tig][c0]);
                    b[nj][1] = __float_as_uint(Bs[kk + tig + 4][c0]);
                }
#pragma unroll
                for (int mi = 0; mi < 2; mi++)
#pragma unroll
                    for (int nj = 0; nj < 4; nj++) {
                        asm volatile(
                            "mma.sync.aligned.m16n8k8.row.col.f32.tf32.tf32.f32 "
                            "{%0,%1,%2,%3}, {%4,%5,%6,%7}, {%8,%9}, {%0,%1,%2,%3};"
                            : "+f"(acc[mi][nj][0]), "+f"(acc[mi][nj][1]),
                              "+f"(acc[mi][nj][2]), "+f"(acc[mi][nj][3])
                            : "r"(a[mi][0]), "r"(a[mi][1]), "r"(a[mi][2]), "r"(a[mi][3]),
                              "r"(b[nj][0]), "r"(b[nj][1]));
                    }
            }
            __syncthreads();
        }
    }

    float* C = (MODE == 0) ? d_h1 : d_h2;
#pragma unroll
    for (int mi = 0; mi < 2; mi++) {
#pragma unroll
        for (int nj = 0; nj < 4; nj++) {
            int row = rowBase + wm + mi * 16 + g;
            int col = colBase + wn + nj * 8 + tig * 2;
            if (row < M)
                *(float2*)&C[(size_t)row * N + col] =
                    make_float2(acc[mi][nj][0], acc[mi][nj][1]);
            if (row + 8 < M)
                *(float2*)&C[(size_t)(row + 8) * N + col] =
                    make_float2(acc[mi][nj][2], acc[mi][nj][3]);
        }
    }
}

// ---------------- attention dot products ----------------
__global__ void k_attn1(const float* __restrict__ att_s, const float* __restrict__ att_d) {
    int n = blockIdx.x;
    int w = threadIdx.x / 32, l = threadIdx.x % 32;
    const float* hp = &d_h1[(size_t)n * W1COLS + w * HID];
    float ss = 0.f, dd = 0.f;
#pragma unroll
    for (int i = 0; i < 4; i++) {
        float v = hp[l + i * 32];
        ss = fmaf(v, att_s[w * HID + l + i * 32], ss);
        dd = fmaf(v, att_d[w * HID + l + i * 32], dd);
    }
#pragma unroll
    for (int off = 16; off; off >>= 1) {
        ss += __shfl_down_sync(0xffffffffu, ss, off);
        dd += __shfl_down_sync(0xffffffffu, dd, off);
    }
    if (l == 0) { d_as1[n * HEADSN + w] = ss; d_ad1[n * HEADSN + w] = dd; }
}

__global__ void k_attn2(const float* __restrict__ att_s, const float* __restrict__ att_d) {
    int n = blockIdx.x;
    int l = threadIdx.x;
    const float* hp = &d_h2[(size_t)n * DOUT];
    float ss = 0.f, dd = 0.f;
#pragma unroll
    for (int i = 0; i < 4; i++) {
        float v = hp[l + i * 32];
        ss = fmaf(v, att_s[l + i * 32], ss);
        dd = fmaf(v, att_d[l + i * 32], dd);
    }
#pragma unroll
    for (int off = 16; off; off >>= 1) {
        ss += __shfl_down_sync(0xffffffffu, ss, off);
        dd += __shfl_down_sync(0xffffffffu, dd, off);
    }
    if (l == 0) { d_as2[n] = ss; d_ad2[n] = dd; }
}

// ---------------- per-dst softmax aggregation (single pass; softmax is
// shift-invariant and logits are O(1), so no max subtraction needed) ----------
template <int LAYER>
__global__ __launch_bounds__(128) void k_agg(const float* __restrict__ bias,
                                             float* __restrict__ outp)
{
    constexpr int H = (LAYER == 0) ? HEADSN : 1;
    constexpr int C = 128;
    const float* h    = (LAYER == 0) ? d_h1 : d_h2;
    const float* asv  = (LAYER == 0) ? d_as1 : d_as2;
    const float* advv = (LAYER == 0) ? d_ad1 : d_ad2;
    float* out        = (LAYER == 0) ? d_agg1 : outp;

    int n = blockIdx.x;
    int t = threadIdx.x;
    int beg = d_offsets[n], end = d_offsets[n + 1];

    float adv[H];
#pragma unroll
    for (int hh = 0; hh < H; hh++) adv[hh] = advv[n * H + hh];

    float denom[H], acc[H];
#pragma unroll
    for (int hh = 0; hh < H; hh++) { denom[hh] = 0.f; acc[hh] = 0.f; }

    for (int e = beg; e < end; e++) {
        int s = d_csr_src[e];
        const float* hr = &h[(size_t)s * (H * C)];
#pragma unroll
        for (int hh = 0; hh < H; hh++) {
            float ev = asv[s * H + hh] + adv[hh];
            ev = ev > 0.f ? ev : 0.2f * ev;
            float p = __expf(ev);
            denom[hh] += p;
            acc[hh] = fmaf(p, hr[hh * C + t], acc[hh]);
        }
    }

#pragma unroll
    for (int hh = 0; hh < H; hh++) {
        float v = acc[hh] / (denom[hh] + 1e-16f) + bias[hh * C + t];
        if (LAYER == 0) v = v > 0.f ? v : expm1f(v);
        out[(size_t)n * (H * C) + hh * C + t] = v;
    }
}

// ---------------- host side ----------------
extern "C" void kernel_launch(void* const* d_in, const int* in_sizes, int n_in,
                              void* d_out, int out_size) {
    const float* x    = (const float*)d_in[0];
    const int*   ei   = (const int*)d_in[1];
    const int*   et   = (const int*)d_in[2];
    const float* rel  = (const float*)d_in[3];
    const float* W1   = (const float*)d_in[4];
    const float* as1w = (const float*)d_in[5];
    const float* ad1w = (const float*)d_in[6];
    const float* b1   = (const float*)d_in[7];
    const float* W2   = (const float*)d_in[8];
    const float* as2w = (const float*)d_in[9];
    const float* ad2w = (const float*)d_in[10];
    const float* b2   = (const float*)d_in[11];
    float*       out  = (float*)d_out;

    k_init<<<(NN * RR + 255) / 256, 256>>>();
    k_hist<<<(EE + 255) / 256, 256>>>(ei, et);
    k_scan<<<1, 1024>>>();
    k_fill<<<(E2 + 255) / 256, 256>>>(ei);

    k_rw1<<<RR, W1COLS>>>(rel, W1);

    {
        dim3 grid(W1COLS / 64, (NN + 127) / 128);
        k_gemm_tc<0><<<grid, 256>>>(x, W1);
    }
    k_attn1<<<NN, 128>>>(as1w, ad1w);
    k_agg<0><<<NN, 128>>>(b1, nullptr);

    {
        dim3 grid(DOUT / 64, (NN + 127) / 128);
        k_gemm_tc<1><<<grid, 256>>>(nullptr, W2);
    }
    k_attn2<<<NN, 32>>>(as2w, ad2w);
    k_agg<1><<<NN, 128>>>(b2, out);
}

// round 5
// speedup vs baseline: 1.6290x; 1.0830x over previous
#include <cuda_runtime.h>
#include <math.h>
#include <stdint.h>

#define NN 20000
#define EE 640000
#define DIN 256
#define HID 128
#define HEADSN 4
#define DOUT 128
#define RR 32
#define E2 (EE + NN)
#define W1COLS (HEADSN * HID)   // 512

// ---------------- scratch ----------------
__device__ __align__(256) float d_counts[NN * RR];
__device__ __align__(256) int   d_deg[NN];
__device__ __align__(256) int   d_offsets[NN + 1];
__device__ __align__(256) int   d_cursor[NN];
__device__ __align__(256) int   d_csr_src[E2];
__device__ __align__(256) int   d_csr_dst[E2];
__device__ __align__(256) float d_RW1[RR * W1COLS];
__device__ __align__(256) float d_h1[(size_t)NN * W1COLS];
__device__ __align__(256) float d_as1[NN * HEADSN];
__device__ __align__(256) float d_ad1[NN * HEADSN];
__device__ __align__(256) float d_w1[(size_t)E2 * HEADSN];   // exp weights layer 1
__device__ __align__(256) float d_agg1[(size_t)NN * W1COLS];
__device__ __align__(256) float d_h2[(size_t)NN * DOUT];
__device__ __align__(256) float d_as2[NN];
__device__ __align__(256) float d_ad2[NN];
__device__ __align__(256) float d_w2[E2];                    // exp weights layer 2

__device__ __forceinline__ float to_tf32(float x) {
    uint32_t r;
    asm("cvt.rna.tf32.f32 %0, %1;" : "=r"(r) : "f"(x));
    return __uint_as_float(r);
}

// ---------------- init ----------------
__global__ void k_init() {
    int i = blockIdx.x * blockDim.x + threadIdx.x;
    if (i < NN * RR) d_counts[i] = 0.f;
    if (i < NN) { d_deg[i] = 1; d_cursor[i] = 0; }
}

// ---------------- histogram ----------------
__global__ void k_hist(const int* __restrict__ ei, const int* __restrict__ et) {
    int e = blockIdx.x * blockDim.x + threadIdx.x;
    if (e < EE) {
        int s = ei[e];
        int d = ei[EE + e];
        int r = et[e];
        atomicAdd(&d_counts[s * RR + r], 1.0f);
        atomicAdd(&d_deg[d], 1);
    }
}

// ---------------- exclusive scan (single block, shuffle-based) ----------------
__global__ __launch_bounds__(1024) void k_scan() {
    const int PER = 20;
    int t = threadIdx.x;
    int lane = t & 31, w = t >> 5;
    int base = t * PER;

    int loc[PER];
    int sum = 0;
#pragma unroll
    for (int i = 0; i < PER; i++) {
        int idx = base + i;
        int v = (idx < NN) ? d_deg[idx] : 0;
        loc[i] = sum;
        sum += v;
    }
    int incl = sum;
#pragma unroll
    for (int off = 1; off < 32; off <<= 1) {
        int u = __shfl_up_sync(0xffffffffu, incl, off);
        if (lane >= off) incl += u;
    }
    __shared__ int wincl[32];
    if (lane == 31) wincl[w] = incl;
    __syncthreads();
    if (w == 0) {
        int v = wincl[lane];
        int wi = v;
#pragma unroll
        for (int off = 1; off < 32; off <<= 1) {
            int u = __shfl_up_sync(0xffffffffu, wi, off);
            if (lane >= off) wi += u;
        }
        wincl[lane] = wi;
    }
    __syncthreads();
    int warp_excl = (w == 0) ? 0 : wincl[w - 1];
    int thread_excl = warp_excl + (incl - sum);
#pragma unroll
    for (int i = 0; i < PER; i++) {
        int idx = base + i;
        if (idx < NN) d_offsets[idx] = thread_excl + loc[i];
    }
    if (t == 0) d_offsets[NN] = wincl[31];
}

// ---------------- CSR fill (records src AND dst per slot) ----------------
__global__ void k_fill(const int* __restrict__ ei) {
    int e = blockIdx.x * blockDim.x + threadIdx.x;
    if (e < EE) {
        int s = ei[e];
        int d = ei[EE + e];
        int pos = d_offsets[d] + atomicAdd(&d_cursor[d], 1);
        d_csr_src[pos] = s;
        d_csr_dst[pos] = d;
    } else if (e < E2) {
        int n = e - EE;
        int pos = d_offsets[n] + atomicAdd(&d_cursor[n], 1);
        d_csr_src[pos] = n;
        d_csr_dst[pos] = n;
    }
}

// ---------------- RW1 = rel_emb @ W1 ----------------
__global__ void k_rw1(const float* __restrict__ rel, const float* __restrict__ W1) {
    int r = blockIdx.x;
    int j = threadIdx.x;
    float acc = 0.f;
    const float* rr = rel + r * DIN;
    for (int k = 0; k < DIN; k++)
        acc = fmaf(rr[k], W1[(size_t)k * W1COLS + j], acc);
    d_RW1[r * W1COLS + j] = acc;
}

// ---------------- TF32 tensor-core GEMM (as R4) ------------------------------
template <int MODE>
__global__ __launch_bounds__(256) void k_gemm_tc(const float* __restrict__ A0,
                                                 const float* __restrict__ B0)
{
    constexpr int M = NN;
    constexpr int N = (MODE == 0) ? W1COLS : DOUT;
    constexpr int NPASS = (MODE == 0) ? 2 : 1;
    constexpr int BM = 128, BK = 16;

    __shared__ float As[BM][BK + 1];
    __shared__ float Bs[BK][64 + 4];

    int tid = threadIdx.x;
    int lane = tid & 31, wid = tid >> 5;
    int wm = (wid & 3) * 32;
    int wn = (wid >> 2) * 32;
    int g = lane >> 2, tig = lane & 3;

    int rowBase = blockIdx.y * BM;
    int colBase = blockIdx.x * 64;

    int la_r = tid >> 1;
    int la_c = (tid & 1) * 8;
    int lb_r = tid >> 4;
    int lb_c = (tid & 15) * 4;

    float acc[2][4][4];
#pragma unroll
    for (int mi = 0; mi < 2; mi++)
#pragma unroll
        for (int nj = 0; nj < 4; nj++)
#pragma unroll
            for (int q = 0; q < 4; q++) acc[mi][nj][q] = 0.f;

#pragma unroll
    for (int pass = 0; pass < NPASS; pass++) {
        const float* Ap;
        const float* Bp;
        int Kp;
        if (MODE == 0) {
            if (pass == 0) { Ap = A0; Bp = B0; Kp = DIN; }
            else           { Ap = d_counts; Bp = d_RW1; Kp = RR; }
        } else {
            Ap = d_agg1; Bp = B0; Kp = W1COLS;
        }

        for (int k0 = 0; k0 < Kp; k0 += BK) {
            {
                int gr = rowBase + la_r;
                float4 v0 = make_float4(0.f, 0.f, 0.f, 0.f);
                float4 v1 = make_float4(0.f, 0.f, 0.f, 0.f);
                if (gr < M) {
                    const float* ap = &Ap[(size_t)gr * Kp + k0 + la_c];
                    v0 = *(const float4*)ap;
                    v1 = *(const float4*)(ap + 4);
                }
                As[la_r][la_c + 0] = to_tf32(v0.x);
                As[la_r][la_c + 1] = to_tf32(v0.y);
                As[la_r][la_c + 2] = to_tf32(v0.z);
                As[la_r][la_c + 3] = to_tf32(v0.w);
                As[la_r][la_c + 4] = to_tf32(v1.x);
                As[la_r][la_c + 5] = to_tf32(v1.y);
                As[la_r][la_c + 6] = to_tf32(v1.z);
                As[la_r][la_c + 7] = to_tf32(v1.w);
            }
            {
                float4 v = *(const float4*)&Bp[(size_t)(k0 + lb_r) * N + colBase + lb_c];
                Bs[lb_r][lb_c + 0] = to_tf32(v.x);
                Bs[lb_r][lb_c + 1] = to_tf32(v.y);
                Bs[lb_r][lb_c + 2] = to_tf32(v.z);
                Bs[lb_r][lb_c + 3] = to_tf32(v.w);
            }
            __syncthreads();

#pragma unroll
            for (int kk = 0; kk < BK; kk += 8) {
                uint32_t a[2][4];
#pragma unroll
                for (int mi = 0; mi < 2; mi++) {
                    int r0 = wm + mi * 16 + g;
                    a[mi][0] = __float_as_uint(As[r0][kk + tig]);
                    a[mi][1] = __float_as_uint(As[r0 + 8][kk + tig]);
                    a[mi][2] = __float_as_uint(As[r0][kk + tig + 4]);
                    a[mi][3] = __float_as_uint(As[r0 + 8][kk + tig + 4]);
                }
                uint32_t b[4][2];
#pragma unroll
                for (int nj = 0; nj < 4; nj++) {
                    int c0 = wn + nj * 8 + g;
                    b[nj][0] = __float_as_uint(Bs[kk + tig][c0]);
                    b[nj][1] = __float_as_uint(Bs[kk + tig + 4][c0]);
                }
#pragma unroll
                for (int mi = 0; mi < 2; mi++)
#pragma unroll
                    for (int nj = 0; nj < 4; nj++) {
                        asm volatile(
                            "mma.sync.aligned.m16n8k8.row.col.f32.tf32.tf32.f32 "
                            "{%0,%1,%2,%3}, {%4,%5,%6,%7}, {%8,%9}, {%0,%1,%2,%3};"
                            : "+f"(acc[mi][nj][0]), "+f"(acc[mi][nj][1]),
                              "+f"(acc[mi][nj][2]), "+f"(acc[mi][nj][3])
                            : "r"(a[mi][0]), "r"(a[mi][1]), "r"(a[mi][2]), "r"(a[mi][3]),
                              "r"(b[nj][0]), "r"(b[nj][1]));
                    }
            }
            __syncthreads();
        }
    }

    float* C = (MODE == 0) ? d_h1 : d_h2;
#pragma unroll
    for (int mi = 0; mi < 2; mi++) {
#pragma unroll
        for (int nj = 0; nj < 4; nj++) {
            int row = rowBase + wm + mi * 16 + g;
            int col = colBase + wn + nj * 8 + tig * 2;
            if (row < M)
                *(float2*)&C[(size_t)row * N + col] =
                    make_float2(acc[mi][nj][0], acc[mi][nj][1]);
            if (row + 8 < M)
                *(float2*)&C[(size_t)(row + 8) * N + col] =
                    make_float2(acc[mi][nj][2], acc[mi][nj][3]);
        }
    }
}

// ---------------- attention dot products ----------------
__global__ void k_attn1(const float* __restrict__ att_s, const float* __restrict__ att_d) {
    int n = blockIdx.x;
    int w = threadIdx.x / 32, l = threadIdx.x % 32;
    const float* hp = &d_h1[(size_t)n * W1COLS + w * HID];
    float ss = 0.f, dd = 0.f;
#pragma unroll
    for (int i = 0; i < 4; i++) {
        float v = hp[l + i * 32];
        ss = fmaf(v, att_s[w * HID + l + i * 32], ss);
        dd = fmaf(v, att_d[w * HID + l + i * 32], dd);
    }
#pragma unroll
    for (int off = 16; off; off >>= 1) {
        ss += __shfl_down_sync(0xffffffffu, ss, off);
        dd += __shfl_down_sync(0xffffffffu, dd, off);
    }
    if (l == 0) { d_as1[n * HEADSN + w] = ss; d_ad1[n * HEADSN + w] = dd; }
}

__global__ void k_attn2(const float* __restrict__ att_s, const float* __restrict__ att_d) {
    int n = blockIdx.x;
    int l = threadIdx.x;
    const float* hp = &d_h2[(size_t)n * DOUT];
    float ss = 0.f, dd = 0.f;
#pragma unroll
    for (int i = 0; i < 4; i++) {
        float v = hp[l + i * 32];
        ss = fmaf(v, att_s[l + i * 32], ss);
        dd = fmaf(v, att_d[l + i * 32], dd);
    }
#pragma unroll
    for (int off = 16; off; off >>= 1) {
        ss += __shfl_down_sync(0xffffffffu, ss, off);
        dd += __shfl_down_sync(0xffffffffu, dd, off);
    }
    if (l == 0) { d_as2[n] = ss; d_ad2[n] = dd; }
}

// ---------------- edge-parallel softmax weights (one exp per edge-head) ------
// LAYER 0: H=4 -> d_w1[e*4+h].  LAYER 1: H=1 -> d_w2[e].
template <int LAYER>
__global__ void k_wt() {
    int e = blockIdx.x * blockDim.x + threadIdx.x;
    if (e >= E2) return;
    int s = d_csr_src[e];
    int n = d_csr_dst[e];
    if (LAYER == 0) {
#pragma unroll
        for (int hh = 0; hh < HEADSN; hh++) {
            float ev = d_as1[s * HEADSN + hh] + d_ad1[n * HEADSN + hh];
            ev = ev > 0.f ? ev : 0.2f * ev;
            d_w1[(size_t)e * HEADSN + hh] = __expf(ev);
        }
    } else {
        float ev = d_as2[s] + d_ad2[n];
        ev = ev > 0.f ? ev : 0.2f * ev;
        d_w2[e] = __expf(ev);
    }
}

// ---------------- per-dst softmax aggregation (weights precomputed) ----------
template <int LAYER>
__global__ __launch_bounds__(128) void k_agg(const float* __restrict__ bias,
                                             float* __restrict__ outp)
{
    constexpr int H = (LAYER == 0) ? HEADSN : 1;
    constexpr int C = 128;
    const float* h = (LAYER == 0) ? d_h1 : d_h2;
    float* out     = (LAYER == 0) ? d_agg1 : outp;

    int n = blockIdx.x;
    int t = threadIdx.x;
    int beg = d_offsets[n], end = d_offsets[n + 1];

    float denom[H], acc[H];
#pragma unroll
    for (int hh = 0; hh < H; hh++) { denom[hh] = 0.f; acc[hh] = 0.f; }

    for (int e = beg; e < end; e++) {
        int s = d_csr_src[e];
        const float* hr = &h[(size_t)s * (H * C)];
        if (LAYER == 0) {
            float4 w = *(const float4*)&d_w1[(size_t)e * 4];
            denom[0] += w.x; denom[1] += w.y; denom[2] += w.z; denom[3] += w.w;
            acc[0] = fmaf(w.x, hr[0 * C + t], acc[0]);
            acc[1] = fmaf(w.y, hr[1 * C + t], acc[1]);
            acc[2] = fmaf(w.z, hr[2 * C + t], acc[2]);
            acc[3] = fmaf(w.w, hr[3 * C + t], acc[3]);
        } else {
            float w = d_w2[e];
            denom[0] += w;
            acc[0] = fmaf(w, hr[t], acc[0]);
        }
    }

#pragma unroll
    for (int hh = 0; hh < H; hh++) {
        float v = acc[hh] / (denom[hh] + 1e-16f) + bias[hh * C + t];
        if (LAYER == 0) v = v > 0.f ? v : expm1f(v);
        out[(size_t)n * (H * C) + hh * C + t] = v;
    }
}

// ---------------- host side ----------------
extern "C" void kernel_launch(void* const* d_in, const int* in_sizes, int n_in,
                              void* d_out, int out_size) {
    const float* x    = (const float*)d_in[0];
    const int*   ei   = (const int*)d_in[1];
    const int*   et   = (const int*)d_in[2];
    const float* rel  = (const float*)d_in[3];
    const float* W1   = (const float*)d_in[4];
    const float* as1w = (const float*)d_in[5];
    const float* ad1w = (const float*)d_in[6];
    const float* b1   = (const float*)d_in[7];
    const float* W2   = (const float*)d_in[8];
    const float* as2w = (const float*)d_in[9];
    const float* ad2w = (const float*)d_in[10];
    const float* b2   = (const float*)d_in[11];
    float*       out  = (float*)d_out;

    k_init<<<(NN * RR + 255) / 256, 256>>>();
    k_hist<<<(EE + 255) / 256, 256>>>(ei, et);
    k_scan<<<1, 1024>>>();
    k_fill<<<(E2 + 255) / 256, 256>>>(ei);

    k_rw1<<<RR, W1COLS>>>(rel, W1);

    {
        dim3 grid(W1COLS / 64, (NN + 127) / 128);
        k_gemm_tc<0><<<grid, 256>>>(x, W1);
    }
    k_attn1<<<NN, 128>>>(as1w, ad1w);
    k_wt<0><<<(E2 + 255) / 256, 256>>>();
    k_agg<0><<<NN, 128>>>(b1, nullptr);

    {
        dim3 grid(DOUT / 64, (NN + 127) / 128);
        k_gemm_tc<1><<<grid, 256>>>(nullptr, W2);
    }
    k_attn2<<<NN, 32>>>(as2w, ad2w);
    k_wt<1><<<(E2 + 255) / 256, 256>>>();
    k_agg<1><<<NN, 128>>>(b2, out);
}

// round 6
// speedup vs baseline: 1.6734x; 1.0273x over previous
#include <cuda_runtime.h>
#include <cuda_fp16.h>
#include <math.h>
#include <stdint.h>

#define NN 20000
#define EE 640000
#define DIN 256
#define HID 128
#define HEADSN 4
#define DOUT 128
#define RR 32
#define E2 (EE + NN)
#define W1COLS (HEADSN * HID)   // 512

// ---------------- scratch ----------------
__device__ __align__(256) float d_counts[NN * RR];
__device__ __align__(256) int   d_deg[NN];
__device__ __align__(256) int   d_offsets[NN + 1];
__device__ __align__(256) int   d_cursor[NN];
__device__ __align__(256) int   d_csr_src[E2];
__device__ __align__(256) int   d_csr_dst[E2];
__device__ __align__(256) float d_RW1[RR * W1COLS];
__device__ __align__(256) float d_h1[(size_t)NN * W1COLS];
__device__ __align__(256) __half d_h1h[(size_t)NN * W1COLS];   // fp16 gather copy
__device__ __align__(256) float d_as1[NN * HEADSN];
__device__ __align__(256) float d_ad1[NN * HEADSN];
__device__ __align__(256) float d_w1[(size_t)E2 * HEADSN];
__device__ __align__(256) float d_agg1[(size_t)NN * W1COLS];
__device__ __align__(256) float d_h2[(size_t)NN * DOUT];
__device__ __align__(256) __half d_h2h[(size_t)NN * DOUT];     // fp16 gather copy
__device__ __align__(256) float d_as2[NN];
__device__ __align__(256) float d_ad2[NN];
__device__ __align__(256) float d_w2[E2];

__device__ __forceinline__ float to_tf32(float x) {
    uint32_t r;
    asm("cvt.rna.tf32.f32 %0, %1;" : "=r"(r) : "f"(x));
    return __uint_as_float(r);
}

// ---------------- init ----------------
__global__ void k_init() {
    int i = blockIdx.x * blockDim.x + threadIdx.x;
    if (i < NN * RR) d_counts[i] = 0.f;
    if (i < NN) { d_deg[i] = 1; d_cursor[i] = 0; }
}

// ---------------- histogram ----------------
__global__ void k_hist(const int* __restrict__ ei, const int* __restrict__ et) {
    int e = blockIdx.x * blockDim.x + threadIdx.x;
    if (e < EE) {
        int s = ei[e];
        int d = ei[EE + e];
        int r = et[e];
        atomicAdd(&d_counts[s * RR + r], 1.0f);
        atomicAdd(&d_deg[d], 1);
    }
}

// ---------------- exclusive scan (single block, shuffle-based) ----------------
__global__ __launch_bounds__(1024) void k_scan() {
    const int PER = 20;
    int t = threadIdx.x;
    int lane = t & 31, w = t >> 5;
    int base = t * PER;

    int loc[PER];
    int sum = 0;
#pragma unroll
    for (int i = 0; i < PER; i++) {
        int idx = base + i;
        int v = (idx < NN) ? d_deg[idx] : 0;
        loc[i] = sum;
        sum += v;
    }
    int incl = sum;
#pragma unroll
    for (int off = 1; off < 32; off <<= 1) {
        int u = __shfl_up_sync(0xffffffffu, incl, off);
        if (lane >= off) incl += u;
    }
    __shared__ int wincl[32];
    if (lane == 31) wincl[w] = incl;
    __syncthreads();
    if (w == 0) {
        int v = wincl[lane];
        int wi = v;
#pragma unroll
        for (int off = 1; off < 32; off <<= 1) {
            int u = __shfl_up_sync(0xffffffffu, wi, off);
            if (lane >= off) wi += u;
        }
        wincl[lane] = wi;
    }
    __syncthreads();
    int warp_excl = (w == 0) ? 0 : wincl[w - 1];
    int thread_excl = warp_excl + (incl - sum);
#pragma unroll
    for (int i = 0; i < PER; i++) {
        int idx = base + i;
        if (idx < NN) d_offsets[idx] = thread_excl + loc[i];
    }
    if (t == 0) d_offsets[NN] = wincl[31];
}

// ---------------- CSR fill ----------------
__global__ void k_fill(const int* __restrict__ ei) {
    int e = blockIdx.x * blockDim.x + threadIdx.x;
    if (e < EE) {
        int s = ei[e];
        int d = ei[EE + e];
        int pos = d_offsets[d] + atomicAdd(&d_cursor[d], 1);
        d_csr_src[pos] = s;
        d_csr_dst[pos] = d;
    } else if (e < E2) {
        int n = e - EE;
        int pos = d_offsets[n] + atomicAdd(&d_cursor[n], 1);
        d_csr_src[pos] = n;
        d_csr_dst[pos] = n;
    }
}

// ---------------- RW1 = rel_emb @ W1 ----------------
__global__ void k_rw1(const float* __restrict__ rel, const float* __restrict__ W1) {
    int r = blockIdx.x;
    int j = threadIdx.x;
    float acc = 0.f;
    const float* rr = rel + r * DIN;
    for (int k = 0; k < DIN; k++)
        acc = fmaf(rr[k], W1[(size_t)k * W1COLS + j], acc);
    d_RW1[r * W1COLS + j] = acc;
}

// ---------------- TF32 tensor-core GEMM; epilogue writes fp32 + fp16 ---------
template <int MODE>
__global__ __launch_bounds__(256) void k_gemm_tc(const float* __restrict__ A0,
                                                 const float* __restrict__ B0)
{
    constexpr int M = NN;
    constexpr int N = (MODE == 0) ? W1COLS : DOUT;
    constexpr int NPASS = (MODE == 0) ? 2 : 1;
    constexpr int BM = 128, BK = 16;

    __shared__ float As[BM][BK + 1];
    __shared__ float Bs[BK][64 + 4];

    int tid = threadIdx.x;
    int lane = tid & 31, wid = tid >> 5;
    int wm = (wid & 3) * 32;
    int wn = (wid >> 2) * 32;
    int g = lane >> 2, tig = lane & 3;

    int rowBase = blockIdx.y * BM;
    int colBase = blockIdx.x * 64;

    int la_r = tid >> 1;
    int la_c = (tid & 1) * 8;
    int lb_r = tid >> 4;
    int lb_c = (tid & 15) * 4;

    float acc[2][4][4];
#pragma unroll
    for (int mi = 0; mi < 2; mi++)
#pragma unroll
        for (int nj = 0; nj < 4; nj++)
#pragma unroll
            for (int q = 0; q < 4; q++) acc[mi][nj][q] = 0.f;

#pragma unroll
    for (int pass = 0; pass < NPASS; pass++) {
        const float* Ap;
        const float* Bp;
        int Kp;
        if (MODE == 0) {
            if (pass == 0) { Ap = A0; Bp = B0; Kp = DIN; }
            else           { Ap = d_counts; Bp = d_RW1; Kp = RR; }
        } else {
            Ap = d_agg1; Bp = B0; Kp = W1COLS;
        }

        for (int k0 = 0; k0 < Kp; k0 += BK) {
            {
                int gr = rowBase + la_r;
                float4 v0 = make_float4(0.f, 0.f, 0.f, 0.f);
                float4 v1 = make_float4(0.f, 0.f, 0.f, 0.f);
                if (gr < M) {
                    const float* ap = &Ap[(size_t)gr * Kp + k0 + la_c];
                    v0 = *(const float4*)ap;
                    v1 = *(const float4*)(ap + 4);
                }
                As[la_r][la_c + 0] = to_tf32(v0.x);
                As[la_r][la_c + 1] = to_tf32(v0.y);
                As[la_r][la_c + 2] = to_tf32(v0.z);
                As[la_r][la_c + 3] = to_tf32(v0.w);
                As[la_r][la_c + 4] = to_tf32(v1.x);
                As[la_r][la_c + 5] = to_tf32(v1.y);
                As[la_r][la_c + 6] = to_tf32(v1.z);
                As[la_r][la_c + 7] = to_tf32(v1.w);
            }
            {
                float4 v = *(const float4*)&Bp[(size_t)(k0 + lb_r) * N + colBase + lb_c];
                Bs[lb_r][lb_c + 0] = to_tf32(v.x);
                Bs[lb_r][lb_c + 1] = to_tf32(v.y);
                Bs[lb_r][lb_c + 2] = to_tf32(v.z);
                Bs[lb_r][lb_c + 3] = to_tf32(v.w);
            }
            __syncthreads();

#pragma unroll
            for (int kk = 0; kk < BK; kk += 8) {
                uint32_t a[2][4];
#pragma unroll
                for (int mi = 0; mi < 2; mi++) {
                    int r0 = wm + mi * 16 + g;
                    a[mi][0] = __float_as_uint(As[r0][kk + tig]);
                    a[mi][1] = __float_as_uint(As[r0 + 8][kk + tig]);
                    a[mi][2] = __float_as_uint(As[r0][kk + tig + 4]);
                    a[mi][3] = __float_as_uint(As[r0 + 8][kk + tig + 4]);
                }
                uint32_t b[4][2];
#pragma unroll
                for (int nj = 0; nj < 4; nj++) {
                    int c0 = wn + nj * 8 + g;
                    b[nj][0] = __float_as_uint(Bs[kk + tig][c0]);
                    b[nj][1] = __float_as_uint(Bs[kk + tig + 4][c0]);
                }
#pragma unroll
                for (int mi = 0; mi < 2; mi++)
#pragma unroll
                    for (int nj = 0; nj < 4; nj++) {
                        asm volatile(
                            "mma.sync.aligned.m16n8k8.row.col.f32.tf32.tf32.f32 "
                            "{%0,%1,%2,%3}, {%4,%5,%6,%7}, {%8,%9}, {%0,%1,%2,%3};"
                            : "+f"(acc[mi][nj][0]), "+f"(acc[mi][nj][1]),
                              "+f"(acc[mi][nj][2]), "+f"(acc[mi][nj][3])
                            : "r"(a[mi][0]), "r"(a[mi][1]), "r"(a[mi][2]), "r"(a[mi][3]),
                              "r"(b[nj][0]), "r"(b[nj][1]));
                    }
            }
            __syncthreads();
        }
    }

    float*  C  = (MODE == 0) ? d_h1 : d_h2;
    __half* Ch = (MODE == 0) ? d_h1h : d_h2h;
#pragma unroll
    for (int mi = 0; mi < 2; mi++) {
#pragma unroll
        for (int nj = 0; nj < 4; nj++) {
            int row = rowBase + wm + mi * 16 + g;
            int col = colBase + wn + nj * 8 + tig * 2;
            if (row < M) {
                *(float2*)&C[(size_t)row * N + col] =
                    make_float2(acc[mi][nj][0], acc[mi][nj][1]);
                *(__half2*)&Ch[(size_t)row * N + col] =
                    __floats2half2_rn(acc[mi][nj][0], acc[mi][nj][1]);
            }
            if (row + 8 < M) {
                *(float2*)&C[(size_t)(row + 8) * N + col] =
                    make_float2(acc[mi][nj][2], acc[mi][nj][3]);
                *(__half2*)&Ch[(size_t)(row + 8) * N + col] =
                    __floats2half2_rn(acc[mi][nj][2], acc[mi][nj][3]);
            }
        }
    }
}

// ---------------- attention dot products (fp32 inputs -> fp32 logits) --------
__global__ void k_attn1(const float* __restrict__ att_s, const float* __restrict__ att_d) {
    int n = blockIdx.x;
    int w = threadIdx.x / 32, l = threadIdx.x % 32;
    const float* hp = &d_h1[(size_t)n * W1COLS + w * HID];
    float ss = 0.f, dd = 0.f;
#pragma unroll
    for (int i = 0; i < 4; i++) {
        float v = hp[l + i * 32];
        ss = fmaf(v, att_s[w * HID + l + i * 32], ss);
        dd = fmaf(v, att_d[w * HID + l + i * 32], dd);
    }
#pragma unroll
    for (int off = 16; off; off >>= 1) {
        ss += __shfl_down_sync(0xffffffffu, ss, off);
        dd += __shfl_down_sync(0xffffffffu, dd, off);
    }
    if (l == 0) { d_as1[n * HEADSN + w] = ss; d_ad1[n * HEADSN + w] = dd; }
}

__global__ void k_attn2(const float* __restrict__ att_s, const float* __restrict__ att_d) {
    int n = blockIdx.x;
    int l = threadIdx.x;
    const float* hp = &d_h2[(size_t)n * DOUT];
    float ss = 0.f, dd = 0.f;
#pragma unroll
    for (int i = 0; i < 4; i++) {
        float v = hp[l + i * 32];
        ss = fmaf(v, att_s[l + i * 32], ss);
        dd = fmaf(v, att_d[l + i * 32], dd);
    }
#pragma unroll
    for (int off = 16; off; off >>= 1) {
        ss += __shfl_down_sync(0xffffffffu, ss, off);
        dd += __shfl_down_sync(0xffffffffu, dd, off);
    }
    if (l == 0) { d_as2[n] = ss; d_ad2[n] = dd; }
}

// ---------------- edge-parallel softmax weights ----------------
template <int LAYER>
__global__ void k_wt() {
    int e = blockIdx.x * blockDim.x + threadIdx.x;
    if (e >= E2) return;
    int s = d_csr_src[e];
    int n = d_csr_dst[e];
    if (LAYER == 0) {
#pragma unroll
        for (int hh = 0; hh < HEADSN; hh++) {
            float ev = d_as1[s * HEADSN + hh] + d_ad1[n * HEADSN + hh];
            ev = ev > 0.f ? ev : 0.2f * ev;
            d_w1[(size_t)e * HEADSN + hh] = __expf(ev);
        }
    } else {
        float ev = d_as2[s] + d_ad2[n];
        ev = ev > 0.f ? ev : 0.2f * ev;
        d_w2[e] = __expf(ev);
    }
}

// ---------------- aggregation layer 1: fp16 gathers, 4 channels/thread -------
// warp w owns head w; thread t owns row elements [4t, 4t+4).
__global__ __launch_bounds__(128) void k_agg1(const float* __restrict__ bias) {
    int n = blockIdx.x;
    int t = threadIdx.x;
    int hh = t >> 5;                      // head = warp
    int elt = t * 4;                      // element base within 512-row
    int beg = d_offsets[n], end = d_offsets[n + 1];

    float denom = 0.f;
    float a0 = 0.f, a1 = 0.f, a2 = 0.f, a3 = 0.f;

    for (int e = beg; e < end; e++) {
        int s = d_csr_src[e];
        float4 w4 = *(const float4*)&d_w1[(size_t)e * 4];
        float wv = (hh == 0) ? w4.x : (hh == 1) ? w4.y : (hh == 2) ? w4.z : w4.w;
        const __half2* hp = (const __half2*)&d_h1h[(size_t)s * W1COLS + elt];
        __half2 v01 = hp[0];
        __half2 v23 = hp[1];
        float2 f01 = __half22float2(v01);
        float2 f23 = __half22float2(v23);
        denom += wv;
        a0 = fmaf(wv, f01.x, a0);
        a1 = fmaf(wv, f01.y, a1);
        a2 = fmaf(wv, f23.x, a2);
        a3 = fmaf(wv, f23.y, a3);
    }

    float inv = 1.f / (denom + 1e-16f);
    float o0 = a0 * inv + bias[elt + 0];
    float o1 = a1 * inv + bias[elt + 1];
    float o2 = a2 * inv + bias[elt + 2];
    float o3 = a3 * inv + bias[elt + 3];
    o0 = o0 > 0.f ? o0 : expm1f(o0);
    o1 = o1 > 0.f ? o1 : expm1f(o1);
    o2 = o2 > 0.f ? o2 : expm1f(o2);
    o3 = o3 > 0.f ? o3 : expm1f(o3);
    float* op = &d_agg1[(size_t)n * W1COLS + elt];
    *(float4*)op = make_float4(o0, o1, o2, o3);
}

// ---------------- aggregation layer 2: fp16 gathers ----------------
__global__ __launch_bounds__(128) void k_agg2(const float* __restrict__ bias,
                                              float* __restrict__ out) {
    int n = blockIdx.x;
    int t = threadIdx.x;
    int beg = d_offsets[n], end = d_offsets[n + 1];

    float denom = 0.f, acc = 0.f;
    for (int e = beg; e < end; e++) {
        int s = d_csr_src[e];
        float w = d_w2[e];
        float v = __half2float(d_h2h[(size_t)s * DOUT + t]);
        denom += w;
        acc = fmaf(w, v, acc);
    }
    out[(size_t)n * DOUT + t] = acc / (denom + 1e-16f) + bias[t];
}

// ---------------- host side ----------------
extern "C" void kernel_launch(void* const* d_in, const int* in_sizes, int n_in,
                              void* d_out, int out_size) {
    const float* x    = (const float*)d_in[0];
    const int*   ei   = (const int*)d_in[1];
    const int*   et   = (const int*)d_in[2];
    const float* rel  = (const float*)d_in[3];
    const float* W1   = (const float*)d_in[4];
    const float* as1w = (const float*)d_in[5];
    const float* ad1w = (const float*)d_in[6];
    const float* b1   = (const float*)d_in[7];
    const float* W2   = (const float*)d_in[8];
    const float* as2w = (const float*)d_in[9];
    const float* ad2w = (const float*)d_in[10];
    const float* b2   = (const float*)d_in[11];
    float*       out  = (float*)d_out;

    k_init<<<(NN * RR + 255) / 256, 256>>>();
    k_hist<<<(EE + 255) / 256, 256>>>(ei, et);
    k_scan<<<1, 1024>>>();
    k_fill<<<(E2 + 255) / 256, 256>>>(ei);

    k_rw1<<<RR, W1COLS>>>(rel, W1);

    {
        dim3 grid(W1COLS / 64, (NN + 127) / 128);
        k_gemm_tc<0><<<grid, 256>>>(x, W1);
    }
    k_attn1<<<NN, 128>>>(as1w, ad1w);
    k_wt<0><<<(E2 + 255) / 256, 256>>>();
    k_agg1<<<NN, 128>>>(b1);

    {
        dim3 grid(DOUT / 64, (NN + 127) / 128);
        k_gemm_tc<1><<<grid, 256>>>(nullptr, W2);
    }
    k_attn2<<<NN, 32>>>(as2w, ad2w);
    k_wt<1><<<(E2 + 255) / 256, 256>>>();
    k_agg2<<<NN, 128>>>(b2, out);
}

// round 7
// speedup vs baseline: 1.8220x; 1.0888x over previous
#include <cuda_runtime.h>
#include <cuda_fp16.h>
#include <math.h>
#include <stdint.h>

#define NN 20000
#define EE 640000
#define DIN 256
#define HID 128
#define HEADSN 4
#define DOUT 128
#define RR 32
#define E2 (EE + NN)
#define W1COLS (HEADSN * HID)   // 512

// ---------------- scratch ----------------
__device__ __align__(256) float d_counts[NN * RR];
__device__ __align__(256) int   d_deg[NN];
__device__ __align__(256) int   d_offsets[NN + 1];
__device__ __align__(256) int   d_cursor[NN];
__device__ __align__(256) int   d_csr_src[E2];
__device__ __align__(256) int   d_csr_dst[E2];
__device__ __align__(256) float d_RW1[RR * W1COLS];
__device__ __align__(256) float d_h1[(size_t)NN * W1COLS];
__device__ __align__(256) __half d_h1h[(size_t)NN * W1COLS];
__device__ __align__(256) float d_as1[NN * HEADSN];
__device__ __align__(256) float d_ad1[NN * HEADSN];
__device__ __align__(256) float d_w1[(size_t)E2 * HEADSN];
__device__ __align__(256) float d_agg1[(size_t)NN * W1COLS];
__device__ __align__(256) float d_h2[(size_t)NN * DOUT];
__device__ __align__(256) __half d_h2h[(size_t)NN * DOUT];
__device__ __align__(256) float d_as2[NN];
__device__ __align__(256) float d_ad2[NN];
__device__ __align__(256) float d_w2[E2];

__device__ __forceinline__ float to_tf32(float x) {
    uint32_t r;
    asm("cvt.rna.tf32.f32 %0, %1;" : "=r"(r) : "f"(x));
    return __uint_as_float(r);
}

// ---------------- init ----------------
__global__ void k_init() {
    int i = blockIdx.x * blockDim.x + threadIdx.x;
    if (i < NN * RR) d_counts[i] = 0.f;
    if (i < NN) { d_deg[i] = 1; d_cursor[i] = 0; }
}

// ---------------- histogram ----------------
__global__ void k_hist(const int* __restrict__ ei, const int* __restrict__ et) {
    int e = blockIdx.x * blockDim.x + threadIdx.x;
    if (e < EE) {
        int s = ei[e];
        int d = ei[EE + e];
        int r = et[e];
        atomicAdd(&d_counts[s * RR + r], 1.0f);
        atomicAdd(&d_deg[d], 1);
    }
}

// ---------------- exclusive scan ----------------
__global__ __launch_bounds__(1024) void k_scan() {
    const int PER = 20;
    int t = threadIdx.x;
    int lane = t & 31, w = t >> 5;
    int base = t * PER;

    int loc[PER];
    int sum = 0;
#pragma unroll
    for (int i = 0; i < PER; i++) {
        int idx = base + i;
        int v = (idx < NN) ? d_deg[idx] : 0;
        loc[i] = sum;
        sum += v;
    }
    int incl = sum;
#pragma unroll
    for (int off = 1; off < 32; off <<= 1) {
        int u = __shfl_up_sync(0xffffffffu, incl, off);
        if (lane >= off) incl += u;
    }
    __shared__ int wincl[32];
    if (lane == 31) wincl[w] = incl;
    __syncthreads();
    if (w == 0) {
        int v = wincl[lane];
        int wi = v;
#pragma unroll
        for (int off = 1; off < 32; off <<= 1) {
            int u = __shfl_up_sync(0xffffffffu, wi, off);
            if (lane >= off) wi += u;
        }
        wincl[lane] = wi;
    }
    __syncthreads();
    int warp_excl = (w == 0) ? 0 : wincl[w - 1];
    int thread_excl = warp_excl + (incl - sum);
#pragma unroll
    for (int i = 0; i < PER; i++) {
        int idx = base + i;
        if (idx < NN) d_offsets[idx] = thread_excl + loc[i];
    }
    if (t == 0) d_offsets[NN] = wincl[31];
}

// ---------------- CSR fill ----------------
__global__ void k_fill(const int* __restrict__ ei) {
    int e = blockIdx.x * blockDim.x + threadIdx.x;
    if (e < EE) {
        int s = ei[e];
        int d = ei[EE + e];
        int pos = d_offsets[d] + atomicAdd(&d_cursor[d], 1);
        d_csr_src[pos] = s;
        d_csr_dst[pos] = d;
    } else if (e < E2) {
        int n = e - EE;
        int pos = d_offsets[n] + atomicAdd(&d_cursor[n], 1);
        d_csr_src[pos] = n;
        d_csr_dst[pos] = n;
    }
}

// ---------------- RW1 = rel_emb @ W1 ----------------
__global__ void k_rw1(const float* __restrict__ rel, const float* __restrict__ W1) {
    int r = blockIdx.x;
    int j = threadIdx.x;
    float acc = 0.f;
    const float* rr = rel + r * DIN;
    for (int k = 0; k < DIN; k++)
        acc = fmaf(rr[k], W1[(size_t)k * W1COLS + j], acc);
    d_RW1[r * W1COLS + j] = acc;
}

// ---------------- TF32 tensor-core GEMM, register-prefetch pipelined ---------
template <int MODE>
__global__ __launch_bounds__(256) void k_gemm_tc(const float* __restrict__ A0,
                                                 const float* __restrict__ B0)
{
    constexpr int M = NN;
    constexpr int N = (MODE == 0) ? W1COLS : DOUT;
    constexpr int NPASS = (MODE == 0) ? 2 : 1;
    constexpr int BM = 128, BK = 16;

    __shared__ float As[BM][BK + 1];
    __shared__ float Bs[BK][64 + 4];

    int tid = threadIdx.x;
    int lane = tid & 31, wid = tid >> 5;
    int wm = (wid & 3) * 32;
    int wn = (wid >> 2) * 32;
    int g = lane >> 2, tig = lane & 3;

    int rowBase = blockIdx.y * BM;
    int colBase = blockIdx.x * 64;

    int la_r = tid >> 1;
    int la_c = (tid & 1) * 8;
    int lb_r = tid >> 4;
    int lb_c = (tid & 15) * 4;

    float acc[2][4][4];
#pragma unroll
    for (int mi = 0; mi < 2; mi++)
#pragma unroll
        for (int nj = 0; nj < 4; nj++)
#pragma unroll
            for (int q = 0; q < 4; q++) acc[mi][nj][q] = 0.f;

#pragma unroll
    for (int pass = 0; pass < NPASS; pass++) {
        const float* Ap;
        const float* Bp;
        int Kp;
        if (MODE == 0) {
            if (pass == 0) { Ap = A0; Bp = B0; Kp = DIN; }
            else           { Ap = d_counts; Bp = d_RW1; Kp = RR; }
        } else {
            Ap = d_agg1; Bp = B0; Kp = W1COLS;
        }

        int gr = rowBase + la_r;
        const float* aBase = (gr < M) ? &Ap[(size_t)gr * Kp + la_c] : nullptr;
        const float* bBase = &Bp[(size_t)lb_r * N + colBase + lb_c];

        // prefetch first tile into registers
        float4 pa0 = make_float4(0.f, 0.f, 0.f, 0.f);
        float4 pa1 = make_float4(0.f, 0.f, 0.f, 0.f);
        float4 pb;
        if (aBase) { pa0 = *(const float4*)aBase; pa1 = *(const float4*)(aBase + 4); }
        pb = *(const float4*)bBase;

        int nTiles = Kp / BK;
        for (int kt = 0; kt < nTiles; kt++) {
            // commit prefetched tile to smem (tf32-rounded)
            As[la_r][la_c + 0] = to_tf32(pa0.x);
            As[la_r][la_c + 1] = to_tf32(pa0.y);
            As[la_r][la_c + 2] = to_tf32(pa0.z);
            As[la_r][la_c + 3] = to_tf32(pa0.w);
            As[la_r][la_c + 4] = to_tf32(pa1.x);
            As[la_r][la_c + 5] = to_tf32(pa1.y);
            As[la_r][la_c + 6] = to_tf32(pa1.z);
            As[la_r][la_c + 7] = to_tf32(pa1.w);
            Bs[lb_r][lb_c + 0] = to_tf32(pb.x);
            Bs[lb_r][lb_c + 1] = to_tf32(pb.y);
            Bs[lb_r][lb_c + 2] = to_tf32(pb.z);
            Bs[lb_r][lb_c + 3] = to_tf32(pb.w);
            __syncthreads();

            // prefetch next tile while computing this one
            if (kt + 1 < nTiles) {
                int k0n = (kt + 1) * BK;
                if (aBase) {
                    pa0 = *(const float4*)(aBase + k0n);
                    pa1 = *(const float4*)(aBase + k0n + 4);
                }
                pb = *(const float4*)(bBase + (size_t)k0n * N);
            }

#pragma unroll
            for (int kk = 0; kk < BK; kk += 8) {
                uint32_t a[2][4];
#pragma unroll
                for (int mi = 0; mi < 2; mi++) {
                    int r0 = wm + mi * 16 + g;
                    a[mi][0] = __float_as_uint(As[r0][kk + tig]);
                    a[mi][1] = __float_as_uint(As[r0 + 8][kk + tig]);
                    a[mi][2] = __float_as_uint(As[r0][kk + tig + 4]);
                    a[mi][3] = __float_as_uint(As[r0 + 8][kk + tig + 4]);
                }
                uint32_t b[4][2];
#pragma unroll
                for (int nj = 0; nj < 4; nj++) {
                    int c0 = wn + nj * 8 + g;
                    b[nj][0] = __float_as_uint(Bs[kk + tig][c0]);
                    b[nj][1] = __float_as_uint(Bs[kk + tig + 4][c0]);
                }
#pragma unroll
                for (int mi = 0; mi < 2; mi++)
#pragma unroll
                    for (int nj = 0; nj < 4; nj++) {
                        asm volatile(
                            "mma.sync.aligned.m16n8k8.row.col.f32.tf32.tf32.f32 "
                            "{%0,%1,%2,%3}, {%4,%5,%6,%7}, {%8,%9}, {%0,%1,%2,%3};"
                            : "+f"(acc[mi][nj][0]), "+f"(acc[mi][nj][1]),
                              "+f"(acc[mi][nj][2]), "+f"(acc[mi][nj][3])
                            : "r"(a[mi][0]), "r"(a[mi][1]), "r"(a[mi][2]), "r"(a[mi][3]),
                              "r"(b[nj][0]), "r"(b[nj][1]));
                    }
            }
            __syncthreads();
        }
    }

    float*  C  = (MODE == 0) ? d_h1 : d_h2;
    __half* Ch = (MODE == 0) ? d_h1h : d_h2h;
#pragma unroll
    for (int mi = 0; mi < 2; mi++) {
#pragma unroll
        for (int nj = 0; nj < 4; nj++) {
            int row = rowBase + wm + mi * 16 + g;
            int col = colBase + wn + nj * 8 + tig * 2;
            if (row < M) {
                *(float2*)&C[(size_t)row * N + col] =
                    make_float2(acc[mi][nj][0], acc[mi][nj][1]);
                *(__half2*)&Ch[(size_t)row * N + col] =
                    __floats2half2_rn(acc[mi][nj][0], acc[mi][nj][1]);
            }
            if (row + 8 < M) {
                *(float2*)&C[(size_t)(row + 8) * N + col] =
                    make_float2(acc[mi][nj][2], acc[mi][nj][3]);
                *(__half2*)&Ch[(size_t)(row + 8) * N + col] =
                    __floats2half2_rn(acc[mi][nj][2], acc[mi][nj][3]);
            }
        }
    }
}

// ---------------- attention dot products ----------------
__global__ void k_attn1(const float* __restrict__ att_s, const float* __restrict__ att_d) {
    int n = blockIdx.x;
    int w = threadIdx.x / 32, l = threadIdx.x % 32;
    const float* hp = &d_h1[(size_t)n * W1COLS + w * HID];
    float ss = 0.f, dd = 0.f;
#pragma unroll
    for (int i = 0; i < 4; i++) {
        float v = hp[l + i * 32];
        ss = fmaf(v, att_s[w * HID + l + i * 32], ss);
        dd = fmaf(v, att_d[w * HID + l + i * 32], dd);
    }
#pragma unroll
    for (int off = 16; off; off >>= 1) {
        ss += __shfl_down_sync(0xffffffffu, ss, off);
        dd += __shfl_down_sync(0xffffffffu, dd, off);
    }
    if (l == 0) { d_as1[n * HEADSN + w] = ss; d_ad1[n * HEADSN + w] = dd; }
}

__global__ void k_attn2(const float* __restrict__ att_s, const float* __restrict__ att_d) {
    int n = blockIdx.x;
    int l = threadIdx.x;
    const float* hp = &d_h2[(size_t)n * DOUT];
    float ss = 0.f, dd = 0.f;
#pragma unroll
    for (int i = 0; i < 4; i++) {
        float v = hp[l + i * 32];
        ss = fmaf(v, att_s[l + i * 32], ss);
        dd = fmaf(v, att_d[l + i * 32], dd);
    }
#pragma unroll
    for (int off = 16; off; off >>= 1) {
        ss += __shfl_down_sync(0xffffffffu, ss, off);
        dd += __shfl_down_sync(0xffffffffu, dd, off);
    }
    if (l == 0) { d_as2[n] = ss; d_ad2[n] = dd; }
}

// ---------------- edge-parallel softmax weights ----------------
template <int LAYER>
__global__ void k_wt() {
    int e = blockIdx.x * blockDim.x + threadIdx.x;
    if (e >= E2) return;
    int s = d_csr_src[e];
    int n = d_csr_dst[e];
    if (LAYER == 0) {
        float4 w;
        float ev0 = d_as1[s * HEADSN + 0] + d_ad1[n * HEADSN + 0];
        float ev1 = d_as1[s * HEADSN + 1] + d_ad1[n * HEADSN + 1];
        float ev2 = d_as1[s * HEADSN + 2] + d_ad1[n * HEADSN + 2];
        float ev3 = d_as1[s * HEADSN + 3] + d_ad1[n * HEADSN + 3];
        ev0 = ev0 > 0.f ? ev0 : 0.2f * ev0;
        ev1 = ev1 > 0.f ? ev1 : 0.2f * ev1;
        ev2 = ev2 > 0.f ? ev2 : 0.2f * ev2;
        ev3 = ev3 > 0.f ? ev3 : 0.2f * ev3;
        w.x = __expf(ev0); w.y = __expf(ev1); w.z = __expf(ev2); w.w = __expf(ev3);
        *(float4*)&d_w1[(size_t)e * 4] = w;
    } else {
        float ev = d_as2[s] + d_ad2[n];
        ev = ev > 0.f ? ev : 0.2f * ev;
        d_w2[e] = __expf(ev);
    }
}

// ---------------- aggregation layer 1 (unroll x2, independent chains) --------
__global__ __launch_bounds__(128) void k_agg1(const float* __restrict__ bias) {
    int n = blockIdx.x;
    int t = threadIdx.x;
    int hh = t >> 5;
    int elt = t * 4;
    int beg = d_offsets[n], end = d_offsets[n + 1];

    float dA = 0.f, dB = 0.f;
    float a0 = 0.f, a1 = 0.f, a2 = 0.f, a3 = 0.f;
    float b0 = 0.f, b1 = 0.f, b2 = 0.f, b3 = 0.f;

    int e = beg;
    for (; e + 1 < end; e += 2) {
        int s0 = d_csr_src[e];
        int s1 = d_csr_src[e + 1];
        float4 wA = *(const float4*)&d_w1[(size_t)e * 4];
        float4 wB = *(const float4*)&d_w1[(size_t)(e + 1) * 4];
        float wa = (hh == 0) ? wA.x : (hh == 1) ? wA.y : (hh == 2) ? wA.z : wA.w;
        float wb = (hh == 0) ? wB.x : (hh == 1) ? wB.y : (hh == 2) ? wB.z : wB.w;
        const __half2* hpA = (const __half2*)&d_h1h[(size_t)s0 * W1COLS + elt];
        const __half2* hpB = (const __half2*)&d_h1h[(size_t)s1 * W1COLS + elt];
        __half2 vA01 = hpA[0], vA23 = hpA[1];
        __half2 vB01 = hpB[0], vB23 = hpB[1];
        float2 fA01 = __half22float2(vA01), fA23 = __half22float2(vA23);
        float2 fB01 = __half22float2(vB01), fB23 = __half22float2(vB23);
        dA += wa; dB += wb;
        a0 = fmaf(wa, fA01.x, a0); a1 = fmaf(wa, fA01.y, a1);
        a2 = fmaf(wa, fA23.x, a2); a3 = fmaf(wa, fA23.y, a3);
        b0 = fmaf(wb, fB01.x, b0); b1 = fmaf(wb, fB01.y, b1);
        b2 = fmaf(wb, fB23.x, b2); b3 = fmaf(wb, fB23.y, b3);
    }
    if (e < end) {
        int s0 = d_csr_src[e];
        float4 wA = *(const float4*)&d_w1[(size_t)e * 4];
        float wa = (hh == 0) ? wA.x : (hh == 1) ? wA.y : (hh == 2) ? wA.z : wA.w;
        const __half2* hpA = (const __half2*)&d_h1h[(size_t)s0 * W1COLS + elt];
        __half2 vA01 = hpA[0], vA23 = hpA[1];
        float2 fA01 = __half22float2(vA01), fA23 = __half22float2(vA23);
        dA += wa;
        a0 = fmaf(wa, fA01.x, a0); a1 = fmaf(wa, fA01.y, a1);
        a2 = fmaf(wa, fA23.x, a2); a3 = fmaf(wa, fA23.y, a3);
    }

    float denom = dA + dB;
    float inv = 1.f / (denom + 1e-16f);
    float o0 = (a0 + b0) * inv + bias[elt + 0];
    float o1 = (a1 + b1) * inv + bias[elt + 1];
    float o2 = (a2 + b2) * inv + bias[elt + 2];
    float o3 = (a3 + b3) * inv + bias[elt + 3];
    o0 = o0 > 0.f ? o0 : expm1f(o0);
    o1 = o1 > 0.f ? o1 : expm1f(o1);
    o2 = o2 > 0.f ? o2 : expm1f(o2);
    o3 = o3 > 0.f ? o3 : expm1f(o3);
    *(float4*)&d_agg1[(size_t)n * W1COLS + elt] = make_float4(o0, o1, o2, o3);
}

// ---------------- aggregation layer 2 (unroll x4) ----------------
__global__ __launch_bounds__(128) void k_agg2(const float* __restrict__ bias,
                                              float* __restrict__ out) {
    int n = blockIdx.x;
    int t = threadIdx.x;
    int beg = d_offsets[n], end = d_offsets[n + 1];

    float den0 = 0.f, den1 = 0.f, den2 = 0.f, den3 = 0.f;
    float ac0 = 0.f, ac1 = 0.f, ac2 = 0.f, ac3 = 0.f;

    int e = beg;
    for (; e + 3 < end; e += 4) {
        int s0 = d_csr_src[e], s1 = d_csr_src[e + 1];
        int s2 = d_csr_src[e + 2], s3 = d_csr_src[e + 3];
        float w0 = d_w2[e], w1 = d_w2[e + 1], w2 = d_w2[e + 2], w3 = d_w2[e + 3];
        float v0 = __half2float(d_h2h[(size_t)s0 * DOUT + t]);
        float v1 = __half2float(d_h2h[(size_t)s1 * DOUT + t]);
        float v2 = __half2float(d_h2h[(size_t)s2 * DOUT + t]);
        float v3 = __half2float(d_h2h[(size_t)s3 * DOUT + t]);
        den0 += w0; den1 += w1; den2 += w2; den3 += w3;
        ac0 = fmaf(w0, v0, ac0); ac1 = fmaf(w1, v1, ac1);
        ac2 = fmaf(w2, v2, ac2); ac3 = fmaf(w3, v3, ac3);
    }
    for (; e < end; e++) {
        int s0 = d_csr_src[e];
        float w0 = d_w2[e];
        float v0 = __half2float(d_h2h[(size_t)s0 * DOUT + t]);
        den0 += w0;
        ac0 = fmaf(w0, v0, ac0);
    }

    float denom = (den0 + den1) + (den2 + den3);
    float acc = (ac0 + ac1) + (ac2 + ac3);
    out[(size_t)n * DOUT + t] = acc / (denom + 1e-16f) + bias[t];
}

// ---------------- host side ----------------
extern "C" void kernel_launch(void* const* d_in, const int* in_sizes, int n_in,
                              void* d_out, int out_size) {
    const float* x    = (const float*)d_in[0];
    const int*   ei   = (const int*)d_in[1];
    const int*   et   = (const int*)d_in[2];
    const float* rel  = (const float*)d_in[3];
    const float* W1   = (const float*)d_in[4];
    const float* as1w = (const float*)d_in[5];
    const float* ad1w = (const float*)d_in[6];
    const float* b1   = (const float*)d_in[7];
    const float* W2   = (const float*)d_in[8];
    const float* as2w = (const float*)d_in[9];
    const float* ad2w = (const float*)d_in[10];
    const float* b2   = (const float*)d_in[11];
    float*       out  = (float*)d_out;

    // NOTE: launch order arranged so the heavy GEMM sits in the ncu capture slot.
    k_init<<<(NN * RR + 255) / 256, 256>>>();
    k_hist<<<(EE + 255) / 256, 256>>>(ei, et);
    k_rw1<<<RR, W1COLS>>>(rel, W1);

    {
        dim3 grid(W1COLS / 64, (NN + 127) / 128);
        k_gemm_tc<0><<<grid, 256>>>(x, W1);          // <- capture slot
    }

    k_scan<<<1, 1024>>>();
    k_fill<<<(E2 + 255) / 256, 256>>>(ei);

    k_attn1<<<NN, 128>>>(as1w, ad1w);
    k_wt<0><<<(E2 + 255) / 256, 256>>>();
    k_agg1<<<NN, 128>>>(b1);

    {
        dim3 grid(DOUT / 64, (NN + 127) / 128);
        k_gemm_tc<1><<<grid, 256>>>(nullptr, W2);
    }
    k_attn2<<<NN, 32>>>(as2w, ad2w);
    k_wt<1><<<(E2 + 255) / 256, 256>>>();
    k_agg2<<<NN, 128>>>(b2, out);
}

// round 8
// speedup vs baseline: 1.8601x; 1.0209x over previous
#include <cuda_runtime.h>
#include <cuda_fp16.h>
#include <math.h>
#include <stdint.h>

#define NN 20000
#define EE 640000
#define DIN 256
#define HID 128
#define HEADSN 4
#define DOUT 128
#define RR 32
#define E2 (EE + NN)
#define W1COLS (HEADSN * HID)   // 512

// ---------------- scratch ----------------
__device__ __align__(256) float d_counts[NN * RR];
__device__ __align__(256) int   d_deg[NN];
__device__ __align__(256) int   d_offsets[NN + 1];
__device__ __align__(256) int   d_cursor[NN];
__device__ __align__(256) int   d_csr_src[E2];
__device__ __align__(256) int   d_csr_dst[E2];
__device__ __align__(256) float d_RW1[RR * W1COLS];
__device__ __align__(256) float d_h1[(size_t)NN * W1COLS];
__device__ __align__(256) __half d_h1h[(size_t)NN * W1COLS];
__device__ __align__(256) float d_as1[NN * HEADSN];
__device__ __align__(256) float d_ad1[NN * HEADSN];
__device__ __align__(256) float d_w1[(size_t)E2 * HEADSN];
__device__ __align__(256) float d_agg1[(size_t)NN * W1COLS];
__device__ __align__(256) float d_h2[(size_t)NN * DOUT];
__device__ __align__(256) __half d_h2h[(size_t)NN * DOUT];
__device__ __align__(256) float d_as2[NN];
__device__ __align__(256) float d_ad2[NN];
__device__ __align__(256) float d_w2[E2];

__device__ __forceinline__ float to_tf32(float x) {
    uint32_t r;
    asm("cvt.rna.tf32.f32 %0, %1;" : "=r"(r) : "f"(x));
    return __uint_as_float(r);
}

// ---------------- init ----------------
__global__ void k_init() {
    int i = blockIdx.x * blockDim.x + threadIdx.x;
    if (i < NN * RR) d_counts[i] = 0.f;
    if (i < NN) { d_deg[i] = 1; d_cursor[i] = 0; }
}

// ---------------- histogram ----------------
__global__ void k_hist(const int* __restrict__ ei, const int* __restrict__ et) {
    int e = blockIdx.x * blockDim.x + threadIdx.x;
    if (e < EE) {
        int s = ei[e];
        int d = ei[EE + e];
        int r = et[e];
        atomicAdd(&d_counts[s * RR + r], 1.0f);
        atomicAdd(&d_deg[d], 1);
    }
}

// ---------------- exclusive scan ----------------
__global__ __launch_bounds__(1024) void k_scan() {
    const int PER = 20;
    int t = threadIdx.x;
    int lane = t & 31, w = t >> 5;
    int base = t * PER;

    int loc[PER];
    int sum = 0;
#pragma unroll
    for (int i = 0; i < PER; i++) {
        int idx = base + i;
        int v = (idx < NN) ? d_deg[idx] : 0;
        loc[i] = sum;
        sum += v;
    }
    int incl = sum;
#pragma unroll
    for (int off = 1; off < 32; off <<= 1) {
        int u = __shfl_up_sync(0xffffffffu, incl, off);
        if (lane >= off) incl += u;
    }
    __shared__ int wincl[32];
    if (lane == 31) wincl[w] = incl;
    __syncthreads();
    if (w == 0) {
        int v = wincl[lane];
        int wi = v;
#pragma unroll
        for (int off = 1; off < 32; off <<= 1) {
            int u = __shfl_up_sync(0xffffffffu, wi, off);
            if (lane >= off) wi += u;
        }
        wincl[lane] = wi;
    }
    __syncthreads();
    int warp_excl = (w == 0) ? 0 : wincl[w - 1];
    int thread_excl = warp_excl + (incl - sum);
#pragma unroll
    for (int i = 0; i < PER; i++) {
        int idx = base + i;
        if (idx < NN) d_offsets[idx] = thread_excl + loc[i];
    }
    if (t == 0) d_offsets[NN] = wincl[31];
}

// ---------------- CSR fill ----------------
__global__ void k_fill(const int* __restrict__ ei) {
    int e = blockIdx.x * blockDim.x + threadIdx.x;
    if (e < EE) {
        int s = ei[e];
        int d = ei[EE + e];
        int pos = d_offsets[d] + atomicAdd(&d_cursor[d], 1);
        d_csr_src[pos] = s;
        d_csr_dst[pos] = d;
    } else if (e < E2) {
        int n = e - EE;
        int pos = d_offsets[n] + atomicAdd(&d_cursor[n], 1);
        d_csr_src[pos] = n;
        d_csr_dst[pos] = n;
    }
}

// ---------------- RW1 = rel_emb @ W1 ----------------
__global__ void k_rw1(const float* __restrict__ rel, const float* __restrict__ W1) {
    int r = blockIdx.x;
    int j = threadIdx.x;
    float acc = 0.f;
    const float* rr = rel + r * DIN;
    for (int k = 0; k < DIN; k++)
        acc = fmaf(rr[k], W1[(size_t)k * W1COLS + j], acc);
    d_RW1[r * W1COLS + j] = acc;
}

// ---------------- TF32 tensor-core GEMM: CTA 128x128, warp tile 64x32 --------
// 8 warps (2 m x 4 n). Per kk=8 chunk: 16 A-LDS + 8 B-LDS feed 16 MMAs.
template <int MODE>
__global__ __launch_bounds__(256) void k_gemm_tc(const float* __restrict__ A0,
                                                 const float* __restrict__ B0)
{
    constexpr int M = NN;
    constexpr int N = (MODE == 0) ? W1COLS : DOUT;
    constexpr int NPASS = (MODE == 0) ? 2 : 1;
    constexpr int BM = 128, BN = 128, BK = 16;

    __shared__ float As[BM][BK + 1];       // 8704 B
    __shared__ float Bs[BK][BN + 4];       // 8448 B

    int tid = threadIdx.x;
    int lane = tid & 31, wid = tid >> 5;
    int wm = (wid & 1) * 64;               // warp row offset (0/64)
    int wn = (wid >> 1) * 32;              // warp col offset (0/32/64/96)
    int g = lane >> 2, tig = lane & 3;

    int rowBase = blockIdx.y * BM;
    int colBase = blockIdx.x * BN;

    int la_r = tid >> 1;                   // 0..127
    int la_c = (tid & 1) * 8;              // 0 or 8
    int lb_r = tid >> 4;                   // 0..15
    int lb_c = (tid & 15) * 8;             // 0..120

    float acc[4][4][4];
#pragma unroll
    for (int mi = 0; mi < 4; mi++)
#pragma unroll
        for (int nj = 0; nj < 4; nj++)
#pragma unroll
            for (int q = 0; q < 4; q++) acc[mi][nj][q] = 0.f;

#pragma unroll
    for (int pass = 0; pass < NPASS; pass++) {
        const float* Ap;
        const float* Bp;
        int Kp;
        if (MODE == 0) {
            if (pass == 0) { Ap = A0; Bp = B0; Kp = DIN; }
            else           { Ap = d_counts; Bp = d_RW1; Kp = RR; }
        } else {
            Ap = d_agg1; Bp = B0; Kp = W1COLS;
        }

        int gr = rowBase + la_r;
        const float* aBase = (gr < M) ? &Ap[(size_t)gr * Kp + la_c] : nullptr;
        const float* bBase = &Bp[(size_t)lb_r * N + colBase + lb_c];

        float4 pa0 = make_float4(0.f, 0.f, 0.f, 0.f);
        float4 pa1 = make_float4(0.f, 0.f, 0.f, 0.f);
        float4 pb0, pb1;
        if (aBase) { pa0 = *(const float4*)aBase; pa1 = *(const float4*)(aBase + 4); }
        pb0 = *(const float4*)bBase;
        pb1 = *(const float4*)(bBase + 4);

        int nTiles = Kp / BK;
        for (int kt = 0; kt < nTiles; kt++) {
            As[la_r][la_c + 0] = to_tf32(pa0.x);
            As[la_r][la_c + 1] = to_tf32(pa0.y);
            As[la_r][la_c + 2] = to_tf32(pa0.z);
            As[la_r][la_c + 3] = to_tf32(pa0.w);
            As[la_r][la_c + 4] = to_tf32(pa1.x);
            As[la_r][la_c + 5] = to_tf32(pa1.y);
            As[la_r][la_c + 6] = to_tf32(pa1.z);
            As[la_r][la_c + 7] = to_tf32(pa1.w);
            Bs[lb_r][lb_c + 0] = to_tf32(pb0.x);
            Bs[lb_r][lb_c + 1] = to_tf32(pb0.y);
            Bs[lb_r][lb_c + 2] = to_tf32(pb0.z);
            Bs[lb_r][lb_c + 3] = to_tf32(pb0.w);
            Bs[lb_r][lb_c + 4] = to_tf32(pb1.x);
            Bs[lb_r][lb_c + 5] = to_tf32(pb1.y);
            Bs[lb_r][lb_c + 6] = to_tf32(pb1.z);
            Bs[lb_r][lb_c + 7] = to_tf32(pb1.w);
            __syncthreads();

            if (kt + 1 < nTiles) {
                int k0n = (kt + 1) * BK;
                if (aBase) {
                    pa0 = *(const float4*)(aBase + k0n);
                    pa1 = *(const float4*)(aBase + k0n + 4);
                }
                pb0 = *(const float4*)(bBase + (size_t)k0n * N);
                pb1 = *(const float4*)(bBase + (size_t)k0n * N + 4);
            }

#pragma unroll
            for (int kk = 0; kk < BK; kk += 8) {
                uint32_t a[4][4];
#pragma unroll
                for (int mi = 0; mi < 4; mi++) {
                    int r0 = wm + mi * 16 + g;
                    a[mi][0] = __float_as_uint(As[r0][kk + tig]);
                    a[mi][1] = __float_as_uint(As[r0 + 8][kk + tig]);
                    a[mi][2] = __float_as_uint(As[r0][kk + tig + 4]);
                    a[mi][3] = __float_as_uint(As[r0 + 8][kk + tig + 4]);
                }
                uint32_t b[4][2];
#pragma unroll
                for (int nj = 0; nj < 4; nj++) {
                    int c0 = wn + nj * 8 + g;
                    b[nj][0] = __float_as_uint(Bs[kk + tig][c0]);
                    b[nj][1] = __float_as_uint(Bs[kk + tig + 4][c0]);
                }
#pragma unroll
                for (int mi = 0; mi < 4; mi++)
#pragma unroll
                    for (int nj = 0; nj < 4; nj++) {
                        asm volatile(
                            "mma.sync.aligned.m16n8k8.row.col.f32.tf32.tf32.f32 "
                            "{%0,%1,%2,%3}, {%4,%5,%6,%7}, {%8,%9}, {%0,%1,%2,%3};"
                            : "+f"(acc[mi][nj][0]), "+f"(acc[mi][nj][1]),
                              "+f"(acc[mi][nj][2]), "+f"(acc[mi][nj][3])
                            : "r"(a[mi][0]), "r"(a[mi][1]), "r"(a[mi][2]), "r"(a[mi][3]),
                              "r"(b[nj][0]), "r"(b[nj][1]));
                    }
            }
            __syncthreads();
        }
    }

    float*  C  = (MODE == 0) ? d_h1 : d_h2;
    __half* Ch = (MODE == 0) ? d_h1h : d_h2h;
#pragma unroll
    for (int mi = 0; mi < 4; mi++) {
#pragma unroll
        for (int nj = 0; nj < 4; nj++) {
            int row = rowBase + wm + mi * 16 + g;
            int col = colBase + wn + nj * 8 + tig * 2;
            if (row < M) {
                *(float2*)&C[(size_t)row * N + col] =
                    make_float2(acc[mi][nj][0], acc[mi][nj][1]);
                *(__half2*)&Ch[(size_t)row * N + col] =
                    __floats2half2_rn(acc[mi][nj][0], acc[mi][nj][1]);
            }
            if (row + 8 < M) {
                *(float2*)&C[(size_t)(row + 8) * N + col] =
                    make_float2(acc[mi][nj][2], acc[mi][nj][3]);
                *(__half2*)&Ch[(size_t)(row + 8) * N + col] =
                    __floats2half2_rn(acc[mi][nj][2], acc[mi][nj][3]);
            }
        }
    }
}

// ---------------- attention dot products ----------------
__global__ void k_attn1(const float* __restrict__ att_s, const float* __restrict__ att_d) {
    int n = blockIdx.x;
    int w = threadIdx.x / 32, l = threadIdx.x % 32;
    const float* hp = &d_h1[(size_t)n * W1COLS + w * HID];
    float ss = 0.f, dd = 0.f;
#pragma unroll
    for (int i = 0; i < 4; i++) {
        float v = hp[l + i * 32];
        ss = fmaf(v, att_s[w * HID + l + i * 32], ss);
        dd = fmaf(v, att_d[w * HID + l + i * 32], dd);
    }
#pragma unroll
    for (int off = 16; off; off >>= 1) {
        ss += __shfl_down_sync(0xffffffffu, ss, off);
        dd += __shfl_down_sync(0xffffffffu, dd, off);
    }
    if (l == 0) { d_as1[n * HEADSN + w] = ss; d_ad1[n * HEADSN + w] = dd; }
}

__global__ void k_attn2(const float* __restrict__ att_s, const float* __restrict__ att_d) {
    int n = blockIdx.x;
    int l = threadIdx.x;
    const float* hp = &d_h2[(size_t)n * DOUT];
    float ss = 0.f, dd = 0.f;
#pragma unroll
    for (int i = 0; i < 4; i++) {
        float v = hp[l + i * 32];
        ss = fmaf(v, att_s[l + i * 32], ss);
        dd = fmaf(v, att_d[l + i * 32], dd);
    }
#pragma unroll
    for (int off = 16; off; off >>= 1) {
        ss += __shfl_down_sync(0xffffffffu, ss, off);
        dd += __shfl_down_sync(0xffffffffu, dd, off);
    }
    if (l == 0) { d_as2[n] = ss; d_ad2[n] = dd; }
}

// ---------------- edge-parallel softmax weights ----------------
template <int LAYER>
__global__ void k_wt() {
    int e = blockIdx.x * blockDim.x + threadIdx.x;
    if (e >= E2) return;
    int s = d_csr_src[e];
    int n = d_csr_dst[e];
    if (LAYER == 0) {
        float4 w;
        float ev0 = d_as1[s * HEADSN + 0] + d_ad1[n * HEADSN + 0];
        float ev1 = d_as1[s * HEADSN + 1] + d_ad1[n * HEADSN + 1];
        float ev2 = d_as1[s * HEADSN + 2] + d_ad1[n * HEADSN + 2];
        float ev3 = d_as1[s * HEADSN + 3] + d_ad1[n * HEADSN + 3];
        ev0 = ev0 > 0.f ? ev0 : 0.2f * ev0;
        ev1 = ev1 > 0.f ? ev1 : 0.2f * ev1;
        ev2 = ev2 > 0.f ? ev2 : 0.2f * ev2;
        ev3 = ev3 > 0.f ? ev3 : 0.2f * ev3;
        w.x = __expf(ev0); w.y = __expf(ev1); w.z = __expf(ev2); w.w = __expf(ev3);
        *(float4*)&d_w1[(size_t)e * 4] = w;
    } else {
        float ev = d_as2[s] + d_ad2[n];
        ev = ev > 0.f ? ev : 0.2f * ev;
        d_w2[e] = __expf(ev);
    }
}

// ---------------- aggregation layer 1 (unroll x2) ----------------
__global__ __launch_bounds__(128) void k_agg1(const float* __restrict__ bias) {
    int n = blockIdx.x;
    int t = threadIdx.x;
    int hh = t >> 5;
    int elt = t * 4;
    int beg = d_offsets[n], end = d_offsets[n + 1];

    float dA = 0.f, dB = 0.f;
    float a0 = 0.f, a1 = 0.f, a2 = 0.f, a3 = 0.f;
    float b0 = 0.f, b1 = 0.f, b2 = 0.f, b3 = 0.f;

    int e = beg;
    for (; e + 1 < end; e += 2) {
        int s0 = d_csr_src[e];
        int s1 = d_csr_src[e + 1];
        float4 wA = *(const float4*)&d_w1[(size_t)e * 4];
        float4 wB = *(const float4*)&d_w1[(size_t)(e + 1) * 4];
        float wa = (hh == 0) ? wA.x : (hh == 1) ? wA.y : (hh == 2) ? wA.z : wA.w;
        float wb = (hh == 0) ? wB.x : (hh == 1) ? wB.y : (hh == 2) ? wB.z : wB.w;
        const __half2* hpA = (const __half2*)&d_h1h[(size_t)s0 * W1COLS + elt];
        const __half2* hpB = (const __half2*)&d_h1h[(size_t)s1 * W1COLS + elt];
        __half2 vA01 = hpA[0], vA23 = hpA[1];
        __half2 vB01 = hpB[0], vB23 = hpB[1];
        float2 fA01 = __half22float2(vA01), fA23 = __half22float2(vA23);
        float2 fB01 = __half22float2(vB01), fB23 = __half22float2(vB23);
        dA += wa; dB += wb;
        a0 = fmaf(wa, fA01.x, a0); a1 = fmaf(wa, fA01.y, a1);
        a2 = fmaf(wa, fA23.x, a2); a3 = fmaf(wa, fA23.y, a3);
        b0 = fmaf(wb, fB01.x, b0); b1 = fmaf(wb, fB01.y, b1);
        b2 = fmaf(wb, fB23.x, b2); b3 = fmaf(wb, fB23.y, b3);
    }
    if (e < end) {
        int s0 = d_csr_src[e];
        float4 wA = *(const float4*)&d_w1[(size_t)e * 4];
        float wa = (hh == 0) ? wA.x : (hh == 1) ? wA.y : (hh == 2) ? wA.z : wA.w;
        const __half2* hpA = (const __half2*)&d_h1h[(size_t)s0 * W1COLS + elt];
        __half2 vA01 = hpA[0], vA23 = hpA[1];
        float2 fA01 = __half22float2(vA01), fA23 = __half22float2(vA23);
        dA += wa;
        a0 = fmaf(wa, fA01.x, a0); a1 = fmaf(wa, fA01.y, a1);
        a2 = fmaf(wa, fA23.x, a2); a3 = fmaf(wa, fA23.y, a3);
    }

    float denom = dA + dB;
    float inv = 1.f / (denom + 1e-16f);
    float o0 = (a0 + b0) * inv + bias[elt + 0];
    float o1 = (a1 + b1) * inv + bias[elt + 1];
    float o2 = (a2 + b2) * inv + bias[elt + 2];
    float o3 = (a3 + b3) * inv + bias[elt + 3];
    o0 = o0 > 0.f ? o0 : expm1f(o0);
    o1 = o1 > 0.f ? o1 : expm1f(o1);
    o2 = o2 > 0.f ? o2 : expm1f(o2);
    o3 = o3 > 0.f ? o3 : expm1f(o3);
    *(float4*)&d_agg1[(size_t)n * W1COLS + elt] = make_float4(o0, o1, o2, o3);
}

// ---------------- aggregation layer 2 (unroll x4) ----------------
__global__ __launch_bounds__(128) void k_agg2(const float* __restrict__ bias,
                                              float* __restrict__ out) {
    int n = blockIdx.x;
    int t = threadIdx.x;
    int beg = d_offsets[n], end = d_offsets[n + 1];

    float den0 = 0.f, den1 = 0.f, den2 = 0.f, den3 = 0.f;
    float ac0 = 0.f, ac1 = 0.f, ac2 = 0.f, ac3 = 0.f;

    int e = beg;
    for (; e + 3 < end; e += 4) {
        int s0 = d_csr_src[e], s1 = d_csr_src[e + 1];
        int s2 = d_csr_src[e + 2], s3 = d_csr_src[e + 3];
        float w0 = d_w2[e], w1 = d_w2[e + 1], w2 = d_w2[e + 2], w3 = d_w2[e + 3];
        float v0 = __half2float(d_h2h[(size_t)s0 * DOUT + t]);
        float v1 = __half2float(d_h2h[(size_t)s1 * DOUT + t]);
        float v2 = __half2float(d_h2h[(size_t)s2 * DOUT + t]);
        float v3 = __half2float(d_h2h[(size_t)s3 * DOUT + t]);
        den0 += w0; den1 += w1; den2 += w2; den3 += w3;
        ac0 = fmaf(w0, v0, ac0); ac1 = fmaf(w1, v1, ac1);
        ac2 = fmaf(w2, v2, ac2); ac3 = fmaf(w3, v3, ac3);
    }
    for (; e < end; e++) {
        int s0 = d_csr_src[e];
        float w0 = d_w2[e];
        float v0 = __half2float(d_h2h[(size_t)s0 * DOUT + t]);
        den0 += w0;
        ac0 = fmaf(w0, v0, ac0);
    }

    float denom = (den0 + den1) + (den2 + den3);
    float acc = (ac0 + ac1) + (ac2 + ac3);
    out[(size_t)n * DOUT + t] = acc / (denom + 1e-16f) + bias[t];
}

// ---------------- host side ----------------
extern "C" void kernel_launch(void* const* d_in, const int* in_sizes, int n_in,
                              void* d_out, int out_size) {
    const float* x    = (const float*)d_in[0];
    const int*   ei   = (const int*)d_in[1];
    const int*   et   = (const int*)d_in[2];
    const float* rel  = (const float*)d_in[3];
    const float* W1   = (const float*)d_in[4];
    const float* as1w = (const float*)d_in[5];
    const float* ad1w = (const float*)d_in[6];
    const float* b1   = (const float*)d_in[7];
    const float* W2   = (const float*)d_in[8];
    const float* as2w = (const float*)d_in[9];
    const float* ad2w = (const float*)d_in[10];
    const float* b2   = (const float*)d_in[11];
    float*       out  = (float*)d_out;

    // launch order keeps gemm0 in the ncu capture slot (4th launch)
    k_init<<<(NN * RR + 255) / 256, 256>>>();
    k_hist<<<(EE + 255) / 256, 256>>>(ei, et);
    k_rw1<<<RR, W1COLS>>>(rel, W1);

    {
        dim3 grid(W1COLS / 128, (NN + 127) / 128);
        k_gemm_tc<0><<<grid, 256>>>(x, W1);          // <- capture slot
    }

    k_scan<<<1, 1024>>>();
    k_fill<<<(E2 + 255) / 256, 256>>>(ei);

    k_attn1<<<NN, 128>>>(as1w, ad1w);
    k_wt<0><<<(E2 + 255) / 256, 256>>>();
    k_agg1<<<NN, 128>>>(b1);

    {
        dim3 grid(DOUT / 128, (NN + 127) / 128);
        k_gemm_tc<1><<<grid, 256>>>(nullptr, W2);
    }
    k_attn2<<<NN, 32>>>(as2w, ad2w);
    k_wt<1><<<(E2 + 255) / 256, 256>>>();
    k_agg2<<<NN, 128>>>(b2, out);
}

// round 10
// speedup vs baseline: 2.4116x; 1.2965x over previous
#include <cuda_runtime.h>
#include <cuda_fp16.h>
#include <math.h>
#include <stdint.h>

#define NN 20000
#define EE 640000
#define DIN 256
#define HID 128
#define HEADSN 4
#define DOUT 128
#define RR 32
#define E2 (EE + NN)
#define W1COLS (HEADSN * HID)   // 512

// ---------------- scratch ----------------
__device__ __align__(256) float  d_counts[NN * RR];
__device__ __align__(256) __half d_countsh[NN * RR];
__device__ __align__(256) int    d_deg[NN];
__device__ __align__(256) int    d_offsets[NN + 1];
__device__ __align__(256) int    d_cursor[NN];
__device__ __align__(256) int    d_csr_src[E2];
__device__ __align__(256) int    d_csr_dst[E2];
__device__ __align__(256) __half d_RW1h[RR * W1COLS];
__device__ __align__(256) __half d_xh[(size_t)NN * DIN];
__device__ __align__(256) __half d_W1h[DIN * W1COLS];
__device__ __align__(256) __half d_W2h[W1COLS * DOUT];
__device__ __align__(256) float  d_h1[(size_t)NN * W1COLS];
__device__ __align__(256) __half d_h1h[(size_t)NN * W1COLS];
__device__ __align__(256) float  d_as1[NN * HEADSN];
__device__ __align__(256) float  d_ad1[NN * HEADSN];
__device__ __align__(256) float  d_w1[(size_t)E2 * HEADSN];
__device__ __align__(256) __half d_agg1h[(size_t)NN * W1COLS];
__device__ __align__(256) float  d_h2[(size_t)NN * DOUT];
__device__ __align__(256) __half d_h2h[(size_t)NN * DOUT];
__device__ __align__(256) float  d_as2[NN];
__device__ __align__(256) float  d_ad2[NN];
__device__ __align__(256) float  d_w2[E2];

// ---------------- async copy / ldmatrix helpers ----------------
__device__ __forceinline__ void cp_async16(uint32_t dst, const void* src, int szbytes) {
    asm volatile("cp.async.cg.shared.global [%0], [%1], 16, %2;"
                 :: "r"(dst), "l"(src), "r"(szbytes));
}
__device__ __forceinline__ void cp_commit() { asm volatile("cp.async.commit_group;"); }
template <int NW> __device__ __forceinline__ void cp_wait() {
    asm volatile("cp.async.wait_group %0;" :: "n"(NW));
}
__device__ __forceinline__ void ldsm_x4(uint32_t* r, uint32_t addr) {
    asm volatile("ldmatrix.sync.aligned.m8n8.x4.shared.b16 {%0,%1,%2,%3}, [%4];"
                 : "=r"(r[0]), "=r"(r[1]), "=r"(r[2]), "=r"(r[3]) : "r"(addr));
}
__device__ __forceinline__ void ldsm_x4_t(uint32_t* r, uint32_t addr) {
    asm volatile("ldmatrix.sync.aligned.m8n8.x4.trans.shared.b16 {%0,%1,%2,%3}, [%4];"
                 : "=r"(r[0]), "=r"(r[1]), "=r"(r[2]), "=r"(r[3]) : "r"(addr));
}

// ---------------- init ----------------
__global__ void k_init() {
    int i = blockIdx.x * blockDim.x + threadIdx.x;
    if (i < NN * RR) d_counts[i] = 0.f;
    if (i < NN) { d_deg[i] = 1; d_cursor[i] = 0; }
}

// ---------------- histogram ----------------
__global__ void k_hist(const int* __restrict__ ei, const int* __restrict__ et) {
    int e = blockIdx.x * blockDim.x + threadIdx.x;
    if (e < EE) {
        int s = ei[e];
        int d = ei[EE + e];
        int r = et[e];
        atomicAdd(&d_counts[s * RR + r], 1.0f);
        atomicAdd(&d_deg[d], 1);
    }
}

// ---------------- prep: RW1 gemm + fp16 conversions ----------------
#define PREP_RW1   32
#define PREP_X     1250
#define PREP_CNT   157
#define PREP_W1    32
#define PREP_W2    16
__global__ __launch_bounds__(512) void k_prep(const float* __restrict__ x,
                                              const float* __restrict__ rel,
                                              const float* __restrict__ W1,
                                              const float* __restrict__ W2) {
    int b = blockIdx.x, t = threadIdx.x;
    if (b < PREP_RW1) {
        int r = b, j = t;
        float acc = 0.f;
        const float* rr = rel + r * DIN;
        for (int k = 0; k < DIN; k++)
            acc = fmaf(rr[k], W1[(size_t)k * W1COLS + j], acc);
        d_RW1h[r * W1COLS + j] = __float2half(acc);
    } else if (b < PREP_RW1 + PREP_X) {
        size_t i = (size_t)(b - PREP_RW1) * 4096 + (size_t)t * 8;
#pragma unroll
        for (int q = 0; q < 8; q++) d_xh[i + q] = __float2half(x[i + q]);
    } else if (b < PREP_RW1 + PREP_X + PREP_CNT) {
        size_t i = (size_t)(b - PREP_RW1 - PREP_X) * 4096 + (size_t)t * 8;
#pragma unroll
        for (int q = 0; q < 8; q++)
            if (i + q < (size_t)NN * RR) d_countsh[i + q] = __float2half(d_counts[i + q]);
    } else if (b < PREP_RW1 + PREP_X + PREP_CNT + PREP_W1) {
        size_t i = (size_t)(b - PREP_RW1 - PREP_X - PREP_CNT) * 4096 + (size_t)t * 8;
#pragma unroll
        for (int q = 0; q < 8; q++) d_W1h[i + q] = __float2half(W1[i + q]);
    } else {
        size_t i = (size_t)(b - PREP_RW1 - PREP_X - PREP_CNT - PREP_W1) * 4096 + (size_t)t * 8;
#pragma unroll
        for (int q = 0; q < 8; q++) d_W2h[i + q] = __float2half(W2[i + q]);
    }
}

// ---------------- exclusive scan ----------------
__global__ __launch_bounds__(1024) void k_scan() {
    const int PER = 20;
    int t = threadIdx.x;
    int lane = t & 31, w = t >> 5;
    int base = t * PER;

    int loc[PER];
    int sum = 0;
#pragma unroll
    for (int i = 0; i < PER; i++) {
        int idx = base + i;
        int v = (idx < NN) ? d_deg[idx] : 0;
        loc[i] = sum;
        sum += v;
    }
    int incl = sum;
#pragma unroll
    for (int off = 1; off < 32; off <<= 1) {
        int u = __shfl_up_sync(0xffffffffu, incl, off);
        if (lane >= off) incl += u;
    }
    __shared__ int wincl[32];
    if (lane == 31) wincl[w] = incl;
    __syncthreads();
    if (w == 0) {
        int v = wincl[lane];
        int wi = v;
#pragma unroll
        for (int off = 1; off < 32; off <<= 1) {
            int u = __shfl_up_sync(0xffffffffu, wi, off);
            if (lane >= off) wi += u;
        }
        wincl[lane] = wi;
    }
    __syncthreads();
    int warp_excl = (w == 0) ? 0 : wincl[w - 1];
    int thread_excl = warp_excl + (incl - sum);
#pragma unroll
    for (int i = 0; i < PER; i++) {
        int idx = base + i;
        if (idx < NN) d_offsets[idx] = thread_excl + loc[i];
    }
    if (t == 0) d_offsets[NN] = wincl[31];
}

// ---------------- CSR fill ----------------
__global__ void k_fill(const int* __restrict__ ei) {
    int e = blockIdx.x * blockDim.x + threadIdx.x;
    if (e < EE) {
        int s = ei[e];
        int d = ei[EE + e];
        int pos = d_offsets[d] + atomicAdd(&d_cursor[d], 1);
        d_csr_src[pos] = s;
        d_csr_dst[pos] = d;
    } else if (e < E2) {
        int n = e - EE;
        int pos = d_offsets[n] + atomicAdd(&d_cursor[n], 1);
        d_csr_src[pos] = n;
        d_csr_dst[pos] = n;
    }
}

// ---------------- fp16 tensor-core GEMM: cp.async + ldmatrix -----------------
// CTA 128x128, BK=32, 8 warps (2m x 4n), warp tile 64x32, mma.m16n8k16.f16.
// MODE 0: d_h1 = d_xh@d_W1h + d_countsh@d_RW1h. MODE 1: d_h2 = d_agg1h@d_W2h.
template <int MODE>
__global__ __launch_bounds__(256, 2) void k_gemm_tc()
{
    constexpr int M = NN;
    constexpr int N = (MODE == 0) ? W1COLS : DOUT;
    constexpr int NPASS = (MODE == 0) ? 2 : 1;
    constexpr int BM = 128, BK = 32;
    constexpr int AROW = BK + 8;    // 40 halves
    constexpr int BROW = 128 + 8;   // 136 halves

    __shared__ __half As[2][BM * AROW];
    __shared__ __half Bs[2][BK * BROW];

    int tid = threadIdx.x;
    int lane = tid & 31, wid = tid >> 5;
    int wm = (wid & 1) * 64;
    int wn = (wid >> 1) * 32;
    int g = lane >> 2, tig = lane & 3;

    int rowBase = blockIdx.y * BM;
    int colBase = blockIdx.x * 128;

    uint32_t aSm[2], bSm[2];
    aSm[0] = (uint32_t)__cvta_generic_to_shared(&As[0][0]);
    aSm[1] = (uint32_t)__cvta_generic_to_shared(&As[1][0]);
    bSm[0] = (uint32_t)__cvta_generic_to_shared(&Bs[0][0]);
    bSm[1] = (uint32_t)__cvta_generic_to_shared(&Bs[1][0]);

    int fa_row = tid >> 1;
    int fa_seg = (tid & 1) * 16;
    int fb_row = tid >> 3;
    int fb_seg = (tid & 7) * 16;

    float acc[4][4][4];
#pragma unroll
    for (int mi = 0; mi < 4; mi++)
#pragma unroll
        for (int nj = 0; nj < 4; nj++)
#pragma unroll
            for (int q = 0; q < 4; q++) acc[mi][nj][q] = 0.f;

    int lrow = lane & 15;
    int lcol8 = (lane >> 4) * 8;

#pragma unroll
    for (int pass = 0; pass < NPASS; pass++) {
        const __half* Ap;
        const __half* Bp;
        int Kp;
        if (MODE == 0) {
            if (pass == 0) { Ap = d_xh; Bp = d_W1h; Kp = DIN; }
            else           { Ap = d_countsh; Bp = d_RW1h; Kp = RR; }
        } else {
            Ap = d_agg1h; Bp = d_W2h; Kp = W1COLS;
        }

        int gr = rowBase + fa_row;
        int aOK = (gr < M) ? 16 : 0;
        const __half* aSrc0 = Ap + (size_t)((gr < M) ? gr : (M - 1)) * Kp + fa_seg;
        const __half* bSrc0 = Bp + (size_t)fb_row * N + colBase + fb_seg;
        uint32_t aDst = (uint32_t)(fa_row * AROW + fa_seg) * 2;
        uint32_t bDst = (uint32_t)(fb_row * BROW + fb_seg) * 2;

        int nT = Kp / BK;

        cp_async16(aSm[0] + aDst, aSrc0, aOK);
        cp_async16(aSm[0] + aDst + 16, aSrc0 + 8, aOK);
        cp_async16(bSm[0] + bDst, bSrc0, 16);
        cp_async16(bSm[0] + bDst + 16, bSrc0 + 8, 16);
        cp_commit();

        for (int kt = 0; kt < nT; kt++) {
            if (kt + 1 < nT) {
                int buf = (kt + 1) & 1;
                int k0 = (kt + 1) * BK;
                cp_async16(aSm[buf] + aDst, aSrc0 + k0, aOK);
                cp_async16(aSm[buf] + aDst + 16, aSrc0 + k0 + 8, aOK);
                const __half* bs = bSrc0 + (size_t)k0 * N;
                cp_async16(bSm[buf] + bDst, bs, 16);
                cp_async16(bSm[buf] + bDst + 16, bs + 8, 16);
                cp_commit();
                cp_wait<1>();
            } else {
                cp_wait<0>();
            }
            __syncthreads();

            int buf = kt & 1;
#pragma unroll
            for (int kk = 0; kk < BK; kk += 16) {
                uint32_t a[4][4];
#pragma unroll
                for (int mi = 0; mi < 4; mi++) {
                    uint32_t addr = aSm[buf] +
                        (uint32_t)(((wm + mi * 16 + lrow) * AROW + kk + lcol8) * 2);
                    ldsm_x4(a[mi], addr);
                }
                uint32_t bt[2][4];
#pragma unroll
                for (int p = 0; p < 2; p++) {
                    uint32_t addr = bSm[buf] +
                        (uint32_t)(((kk + lrow) * BROW + wn + p * 16 + lcol8) * 2);
                    ldsm_x4_t(bt[p], addr);
                }
#pragma unroll
                for (int mi = 0; mi < 4; mi++)
#pragma unroll
                    for (int nj = 0; nj < 4; nj++) {
                        uint32_t b0 = bt[nj >> 1][(nj & 1) * 2];
                        uint32_t b1 = bt[nj >> 1][(nj & 1) * 2 + 1];
                        asm volatile(
                            "mma.sync.aligned.m16n8k16.row.col.f32.f16.f16.f32 "
                            "{%0,%1,%2,%3}, {%4,%5,%6,%7}, {%8,%9}, {%0,%1,%2,%3};"
                            : "+f"(acc[mi][nj][0]), "+f"(acc[mi][nj][1]),
                              "+f"(acc[mi][nj][2]), "+f"(acc[mi][nj][3])
                            : "r"(a[mi][0]), "r"(a[mi][1]), "r"(a[mi][2]), "r"(a[mi][3]),
                              "r"(b0), "r"(b1));
                    }
            }
            __syncthreads();
        }
    }

    float*  C  = (MODE == 0) ? d_h1 : d_h2;
    __half* Ch = (MODE == 0) ? d_h1h : d_h2h;
#pragma unroll
    for (int mi = 0; mi < 4; mi++) {
#pragma unroll
        for (int nj = 0; nj < 4; nj++) {
            int row = rowBase + wm + mi * 16 + g;
            int col = colBase + wn + nj * 8 + tig * 2;
            if (row < M) {
                *(float2*)&C[(size_t)row * N + col] =
                    make_float2(acc[mi][nj][0], acc[mi][nj][1]);
                *(__half2*)&Ch[(size_t)row * N + col] =
                    __floats2half2_rn(acc[mi][nj][0], acc[mi][nj][1]);
            }
            if (row + 8 < M) {
                *(float2*)&C[(size_t)(row + 8) * N + col] =
                    make_float2(acc[mi][nj][2], acc[mi][nj][3]);
                *(__half2*)&Ch[(size_t)(row + 8) * N + col] =
                    __floats2half2_rn(acc[mi][nj][2], acc[mi][nj][3]);
            }
        }
    }
}

// ---------------- attention dot products ----------------
__global__ void k_attn1(const float* __restrict__ att_s, const float* __restrict__ att_d) {
    int n = blockIdx.x;
    int w = threadIdx.x / 32, l = threadIdx.x % 32;
    const float* hp = &d_h1[(size_t)n * W1COLS + w * HID];
    float ss = 0.f, dd = 0.f;
#pragma unroll
    for (int i = 0; i < 4; i++) {
        float v = hp[l + i * 32];
        ss = fmaf(v, att_s[w * HID + l + i * 32], ss);
        dd = fmaf(v, att_d[w * HID + l + i * 32], dd);
    }
#pragma unroll
    for (int off = 16; off; off >>= 1) {
        ss += __shfl_down_sync(0xffffffffu, ss, off);
        dd += __shfl_down_sync(0xffffffffu, dd, off);
    }
    if (l == 0) { d_as1[n * HEADSN + w] = ss; d_ad1[n * HEADSN + w] = dd; }
}

__global__ void k_attn2(const float* __restrict__ att_s, const float* __restrict__ att_d) {
    int n = blockIdx.x;
    int l = threadIdx.x;
    const float* hp = &d_h2[(size_t)n * DOUT];
    float ss = 0.f, dd = 0.f;
#pragma unroll
    for (int i = 0; i < 4; i++) {
        float v = hp[l + i * 32];
        ss = fmaf(v, att_s[l + i * 32], ss);
        dd = fmaf(v, att_d[l + i * 32], dd);
    }
#pragma unroll
    for (int off = 16; off; off >>= 1) {
        ss += __shfl_down_sync(0xffffffffu, ss, off);
        dd += __shfl_down_sync(0xffffffffu, dd, off);
    }
    if (l == 0) { d_as2[n] = ss; d_ad2[n] = dd; }
}

// ---------------- edge-parallel softmax weights ----------------
template <int LAYER>
__global__ void k_wt() {
    int e = blockIdx.x * blockDim.x + threadIdx.x;
    if (e >= E2) return;
    int s = d_csr_src[e];
    int n = d_csr_dst[e];
    if (LAYER == 0) {
        float4 w;
        float ev0 = d_as1[s * HEADSN + 0] + d_ad1[n * HEADSN + 0];
        float ev1 = d_as1[s * HEADSN + 1] + d_ad1[n * HEADSN + 1];
        float ev2 = d_as1[s * HEADSN + 2] + d_ad1[n * HEADSN + 2];
        float ev3 = d_as1[s * HEADSN + 3] + d_ad1[n * HEADSN + 3];
        ev0 = ev0 > 0.f ? ev0 : 0.2f * ev0;
        ev1 = ev1 > 0.f ? ev1 : 0.2f * ev1;
        ev2 = ev2 > 0.f ? ev2 : 0.2f * ev2;
        ev3 = ev3 > 0.f ? ev3 : 0.2f * ev3;
        w.x = __expf(ev0); w.y = __expf(ev1); w.z = __expf(ev2); w.w = __expf(ev3);
        *(float4*)&d_w1[(size_t)e * 4] = w;
    } else {
        float ev = d_as2[s] + d_ad2[n];
        ev = ev > 0.f ? ev : 0.2f * ev;
        d_w2[e] = __expf(ev);
    }
}

// ---------------- aggregation layer 1 (fp16 gathers; writes fp16 only) -------
__global__ __launch_bounds__(128) void k_agg1(const float* __restrict__ bias) {
    int n = blockIdx.x;
    int t = threadIdx.x;
    int hh = t >> 5;
    int elt = t * 4;
    int beg = d_offsets[n], end = d_offsets[n + 1];

    float dA = 0.f, dB = 0.f;
    float a0 = 0.f, a1 = 0.f, a2 = 0.f, a3 = 0.f;
    float b0 = 0.f, b1 = 0.f, b2 = 0.f, b3 = 0.f;

    int e = beg;
    for (; e + 1 < end; e += 2) {
        int s0 = d_csr_src[e];
        int s1 = d_csr_src[e + 1];
        float4 wA = *(const float4*)&d_w1[(size_t)e * 4];
        float4 wB = *(const float4*)&d_w1[(size_t)(e + 1) * 4];
        float wa = (hh == 0) ? wA.x : (hh == 1) ? wA.y : (hh == 2) ? wA.z : wA.w;
        float wb = (hh == 0) ? wB.x : (hh == 1) ? wB.y : (hh == 2) ? wB.z : wB.w;
        const __half2* hpA = (const __half2*)&d_h1h[(size_t)s0 * W1COLS + elt];
        const __half2* hpB = (const __half2*)&d_h1h[(size_t)s1 * W1COLS + elt];
        __half2 vA01 = hpA[0], vA23 = hpA[1];
        __half2 vB01 = hpB[0], vB23 = hpB[1];
        float2 fA01 = __half22float2(vA01), fA23 = __half22float2(vA23);
        float2 fB01 = __half22float2(vB01), fB23 = __half22float2(vB23);
        dA += wa; dB += wb;
        a0 = fmaf(wa, fA01.x, a0); a1 = fmaf(wa, fA01.y, a1);
        a2 = fmaf(wa, fA23.x, a2); a3 = fmaf(wa, fA23.y, a3);
        b0 = fmaf(wb, fB01.x, b0); b1 = fmaf(wb, fB01.y, b1);
        b2 = fmaf(wb, fB23.x, b2); b3 = fmaf(wb, fB23.y, b3);
    }
    if (e < end) {
        int s0 = d_csr_src[e];
        float4 wA = *(const float4*)&d_w1[(size_t)e * 4];
        float wa = (hh == 0) ? wA.x : (hh == 1) ? wA.y : (hh == 2) ? wA.z : wA.w;
        const __half2* hpA = (const __half2*)&d_h1h[(size_t)s0 * W1COLS + elt];
        __half2 vA01 = hpA[0], vA23 = hpA[1];
        float2 fA01 = __half22float2(vA01), fA23 = __half22float2(vA23);
        dA += wa;
        a0 = fmaf(wa, fA01.x, a0); a1 = fmaf(wa, fA01.y, a1);
        a2 = fmaf(wa, fA23.x, a2); a3 = fmaf(wa, fA23.y, a3);
    }

    float denom = dA + dB;
    float inv = 1.f / (denom + 1e-16f);
    float o0 = (a0 + b0) * inv + bias[elt + 0];
    float o1 = (a1 + b1) * inv + bias[elt + 1];
    float o2 = (a2 + b2) * inv + bias[elt + 2];
    float o3 = (a3 + b3) * inv + bias[elt + 3];
    o0 = o0 > 0.f ? o0 : expm1f(o0);
    o1 = o1 > 0.f ? o1 : expm1f(o1);
    o2 = o2 > 0.f ? o2 : expm1f(o2);
    o3 = o3 > 0.f ? o3 : expm1f(o3);
    __half2 p01 = __floats2half2_rn(o0, o1);
    __half2 p23 = __floats2half2_rn(o2, o3);
    uint2 pk;
    pk.x = *(uint32_t*)&p01;
    pk.y = *(uint32_t*)&p23;
    *(uint2*)&d_agg1h[(size_t)n * W1COLS + elt] = pk;
}

// ---------------- aggregation layer 2 (unroll x4) ----------------
__global__ __launch_bounds__(128) void k_agg2(const float* __restrict__ bias,
                                              float* __restrict__ out) {
    int n = blockIdx.x;
    int t = threadIdx.x;
    int beg = d_offsets[n], end = d_offsets[n + 1];

    float den0 = 0.f, den1 = 0.f, den2 = 0.f, den3 = 0.f;
    float ac0 = 0.f, ac1 = 0.f, ac2 = 0.f, ac3 = 0.f;

    int e = beg;
    for (; e + 3 < end; e += 4) {
        int s0 = d_csr_src[e], s1 = d_csr_src[e + 1];
        int s2 = d_csr_src[e + 2], s3 = d_csr_src[e + 3];
        float w0 = d_w2[e], w1 = d_w2[e + 1], w2 = d_w2[e + 2], w3 = d_w2[e + 3];
        float v0 = __half2float(d_h2h[(size_t)s0 * DOUT + t]);
        float v1 = __half2float(d_h2h[(size_t)s1 * DOUT + t]);
        float v2 = __half2float(d_h2h[(size_t)s2 * DOUT + t]);
        float v3 = __half2float(d_h2h[(size_t)s3 * DOUT + t]);
        den0 += w0; den1 += w1; den2 += w2; den3 += w3;
        ac0 = fmaf(w0, v0, ac0); ac1 = fmaf(w1, v1, ac1);
        ac2 = fmaf(w2, v2, ac2); ac3 = fmaf(w3, v3, ac3);
    }
    for (; e < end; e++) {
        int s0 = d_csr_src[e];
        float w0 = d_w2[e];
        float v0 = __half2float(d_h2h[(size_t)s0 * DOUT + t]);
        den0 += w0;
        ac0 = fmaf(w0, v0, ac0);
    }

    float denom = (den0 + den1) + (den2 + den3);
    float acc = (ac0 + ac1) + (ac2 + ac3);
    out[(size_t)n * DOUT + t] = acc / (denom + 1e-16f) + bias[t];
}

// ---------------- host side ----------------
extern "C" void kernel_launch(void* const* d_in, const int* in_sizes, int n_in,
                              void* d_out, int out_size) {
    const float* x    = (const float*)d_in[0];
    const int*   ei   = (const int*)d_in[1];
    const int*   et   = (const int*)d_in[2];
    const float* rel  = (const float*)d_in[3];
    const float* W1   = (const float*)d_in[4];
    const float* as1w = (const float*)d_in[5];
    const float* ad1w = (const float*)d_in[6];
    const float* b1   = (const float*)d_in[7];
    const float* W2   = (const float*)d_in[8];
    const float* as2w = (const float*)d_in[9];
    const float* ad2w = (const float*)d_in[10];
    const float* b2   = (const float*)d_in[11];
    float*       out  = (float*)d_out;

    // launch order keeps gemm0 in the ncu capture slot (4th launch)
    k_init<<<(NN * RR + 255) / 256, 256>>>();
    k_hist<<<(EE + 255) / 256, 256>>>(ei, et);
    k_prep<<<PREP_RW1 + PREP_X + PREP_CNT + PREP_W1 + PREP_W2, 512>>>(x, rel, W1, W2);

    {
        dim3 grid(W1COLS / 128, (NN + 127) / 128);
        k_gemm_tc<0><<<grid, 256>>>();               // <- capture slot
    }

    k_scan<<<1, 1024>>>();
    k_fill<<<(E2 + 255) / 256, 256>>>(ei);

    k_attn1<<<NN, 128>>>(as1w, ad1w);
    k_wt<0><<<(E2 + 255) / 256, 256>>>();
    k_agg1<<<NN, 128>>>(b1);

    {
        dim3 grid(DOUT / 128, (NN + 127) / 128);
        k_gemm_tc<1><<<grid, 256>>>();
    }
    k_attn2<<<NN, 32>>>(as2w, ad2w);
    k_wt<1><<<(E2 + 255) / 256, 256>>>();
    k_agg2<<<NN, 128>>>(b2, out);
}

// round 11
// speedup vs baseline: 2.5189x; 1.0445x over previous
#include <cuda_runtime.h>
#include <cuda_fp16.h>
#include <math.h>
#include <stdint.h>

#define NN 20000
#define EE 640000
#define DIN 256
#define HID 128
#define HEADSN 4
#define DOUT 128
#define RR 32
#define E2 (EE + NN)
#define W1COLS (HEADSN * HID)   // 512

// ---------------- scratch ----------------
__device__ __align__(256) float  d_counts[NN * RR];
__device__ __align__(256) __half d_countsh[NN * RR];
__device__ __align__(256) int    d_deg[NN];
__device__ __align__(256) int    d_offsets[NN + 1];
__device__ __align__(256) int    d_cursor[NN];
__device__ __align__(256) int2   d_csr[E2];                    // (src, dst)
__device__ __align__(256) __half d_RW1h[RR * W1COLS];
__device__ __align__(256) __half d_xh[(size_t)NN * DIN];
__device__ __align__(256) __half d_W1h[DIN * W1COLS];
__device__ __align__(256) __half d_W2h[W1COLS * DOUT];
__device__ __align__(256) __half d_h1h[(size_t)NN * W1COLS];
__device__ __align__(256) float  d_as1[NN * HEADSN];
__device__ __align__(256) float  d_ad1[NN * HEADSN];
__device__ __align__(256) float  d_w1[(size_t)E2 * HEADSN];
__device__ __align__(256) __half d_agg1h[(size_t)NN * W1COLS];
__device__ __align__(256) __half d_h2h[(size_t)NN * DOUT];
__device__ __align__(256) float  d_as2[NN];
__device__ __align__(256) float  d_ad2[NN];
__device__ __align__(256) float  d_w2[E2];

// ---------------- async copy / ldmatrix helpers ----------------
__device__ __forceinline__ void cp_async16(uint32_t dst, const void* src, int szbytes) {
    asm volatile("cp.async.cg.shared.global [%0], [%1], 16, %2;"
                 :: "r"(dst), "l"(src), "r"(szbytes));
}
__device__ __forceinline__ void cp_commit() { asm volatile("cp.async.commit_group;"); }
template <int NW> __device__ __forceinline__ void cp_wait() {
    asm volatile("cp.async.wait_group %0;" :: "n"(NW));
}
__device__ __forceinline__ void ldsm_x4(uint32_t* r, uint32_t addr) {
    asm volatile("ldmatrix.sync.aligned.m8n8.x4.shared.b16 {%0,%1,%2,%3}, [%4];"
                 : "=r"(r[0]), "=r"(r[1]), "=r"(r[2]), "=r"(r[3]) : "r"(addr));
}
__device__ __forceinline__ void ldsm_x4_t(uint32_t* r, uint32_t addr) {
    asm volatile("ldmatrix.sync.aligned.m8n8.x4.trans.shared.b16 {%0,%1,%2,%3}, [%4];"
                 : "=r"(r[0]), "=r"(r[1]), "=r"(r[2]), "=r"(r[3]) : "r"(addr));
}

// ---------------- init ----------------
__global__ void k_init() {
    int i = blockIdx.x * blockDim.x + threadIdx.x;
    if (i < NN * RR) d_counts[i] = 0.f;
    if (i < NN) { d_deg[i] = 1; d_cursor[i] = 0; }
}

// ---------------- histogram ----------------
__global__ void k_hist(const int* __restrict__ ei, const int* __restrict__ et) {
    int e = blockIdx.x * blockDim.x + threadIdx.x;
    if (e < EE) {
        int s = ei[e];
        int d = ei[EE + e];
        int r = et[e];
        atomicAdd(&d_counts[s * RR + r], 1.0f);
        atomicAdd(&d_deg[d], 1);
    }
}

// ---------------- prep: RW1 gemm + fp16 conversions ----------------
#define PREP_RW1   32
#define PREP_X     1250
#define PREP_CNT   157
#define PREP_W1    32
#define PREP_W2    16
__global__ __launch_bounds__(512) void k_prep(const float* __restrict__ x,
                                              const float* __restrict__ rel,
                                              const float* __restrict__ W1,
                                              const float* __restrict__ W2) {
    int b = blockIdx.x, t = threadIdx.x;
    if (b < PREP_RW1) {
        int r = b, j = t;
        float acc = 0.f;
        const float* rr = rel + r * DIN;
        for (int k = 0; k < DIN; k++)
            acc = fmaf(rr[k], W1[(size_t)k * W1COLS + j], acc);
        d_RW1h[r * W1COLS + j] = __float2half(acc);
    } else if (b < PREP_RW1 + PREP_X) {
        size_t i = (size_t)(b - PREP_RW1) * 4096 + (size_t)t * 8;
#pragma unroll
        for (int q = 0; q < 8; q++) d_xh[i + q] = __float2half(x[i + q]);
    } else if (b < PREP_RW1 + PREP_X + PREP_CNT) {
        size_t i = (size_t)(b - PREP_RW1 - PREP_X) * 4096 + (size_t)t * 8;
#pragma unroll
        for (int q = 0; q < 8; q++)
            if (i + q < (size_t)NN * RR) d_countsh[i + q] = __float2half(d_counts[i + q]);
    } else if (b < PREP_RW1 + PREP_X + PREP_CNT + PREP_W1) {
        size_t i = (size_t)(b - PREP_RW1 - PREP_X - PREP_CNT) * 4096 + (size_t)t * 8;
#pragma unroll
        for (int q = 0; q < 8; q++) d_W1h[i + q] = __float2half(W1[i + q]);
    } else {
        size_t i = (size_t)(b - PREP_RW1 - PREP_X - PREP_CNT - PREP_W1) * 4096 + (size_t)t * 8;
#pragma unroll
        for (int q = 0; q < 8; q++) d_W2h[i + q] = __float2half(W2[i + q]);
    }
}

// ---------------- exclusive scan ----------------
__global__ __launch_bounds__(1024) void k_scan() {
    const int PER = 20;
    int t = threadIdx.x;
    int lane = t & 31, w = t >> 5;
    int base = t * PER;

    int loc[PER];
    int sum = 0;
#pragma unroll
    for (int i = 0; i < PER; i++) {
        int idx = base + i;
        int v = (idx < NN) ? d_deg[idx] : 0;
        loc[i] = sum;
        sum += v;
    }
    int incl = sum;
#pragma unroll
    for (int off = 1; off < 32; off <<= 1) {
        int u = __shfl_up_sync(0xffffffffu, incl, off);
        if (lane >= off) incl += u;
    }
    __shared__ int wincl[32];
    if (lane == 31) wincl[w] = incl;
    __syncthreads();
    if (w == 0) {
        int v = wincl[lane];
        int wi = v;
#pragma unroll
        for (int off = 1; off < 32; off <<= 1) {
            int u = __shfl_up_sync(0xffffffffu, wi, off);
            if (lane >= off) wi += u;
        }
        wincl[lane] = wi;
    }
    __syncthreads();
    int warp_excl = (w == 0) ? 0 : wincl[w - 1];
    int thread_excl = warp_excl + (incl - sum);
#pragma unroll
    for (int i = 0; i < PER; i++) {
        int idx = base + i;
        if (idx < NN) d_offsets[idx] = thread_excl + loc[i];
    }
    if (t == 0) d_offsets[NN] = wincl[31];
}

// ---------------- CSR fill (packed int2) ----------------
__global__ void k_fill(const int* __restrict__ ei) {
    int e = blockIdx.x * blockDim.x + threadIdx.x;
    if (e < EE) {
        int s = ei[e];
        int d = ei[EE + e];
        int pos = d_offsets[d] + atomicAdd(&d_cursor[d], 1);
        d_csr[pos] = make_int2(s, d);
    } else if (e < E2) {
        int n = e - EE;
        int pos = d_offsets[n] + atomicAdd(&d_cursor[n], 1);
        d_csr[pos] = make_int2(n, n);
    }
}

// ---------------- fp16 tensor-core GEMM: cp.async + ldmatrix -----------------
// CTA 128x128, BK=32, 8 warps (2m x 4n), warp tile 64x32, mma.m16n8k16.f16.
// MODE 0: d_h1h = d_xh@d_W1h + d_countsh@d_RW1h. MODE 1: d_h2h = d_agg1h@d_W2h.
template <int MODE>
__global__ __launch_bounds__(256, 2) void k_gemm_tc()
{
    constexpr int M = NN;
    constexpr int N = (MODE == 0) ? W1COLS : DOUT;
    constexpr int NPASS = (MODE == 0) ? 2 : 1;
    constexpr int BM = 128, BK = 32;
    constexpr int AROW = BK + 8;
    constexpr int BROW = 128 + 8;

    __shared__ __half As[2][BM * AROW];
    __shared__ __half Bs[2][BK * BROW];

    int tid = threadIdx.x;
    int lane = tid & 31, wid = tid >> 5;
    int wm = (wid & 1) * 64;
    int wn = (wid >> 1) * 32;
    int g = lane >> 2, tig = lane & 3;

    int rowBase = blockIdx.y * BM;
    int colBase = blockIdx.x * 128;

    uint32_t aSm[2], bSm[2];
    aSm[0] = (uint32_t)__cvta_generic_to_shared(&As[0][0]);
    aSm[1] = (uint32_t)__cvta_generic_to_shared(&As[1][0]);
    bSm[0] = (uint32_t)__cvta_generic_to_shared(&Bs[0][0]);
    bSm[1] = (uint32_t)__cvta_generic_to_shared(&Bs[1][0]);

    int fa_row = tid >> 1;
    int fa_seg = (tid & 1) * 16;
    int fb_row = tid >> 3;
    int fb_seg = (tid & 7) * 16;

    float acc[4][4][4];
#pragma unroll
    for (int mi = 0; mi < 4; mi++)
#pragma unroll
        for (int nj = 0; nj < 4; nj++)
#pragma unroll
            for (int q = 0; q < 4; q++) acc[mi][nj][q] = 0.f;

    int lrow = lane & 15;
    int lcol8 = (lane >> 4) * 8;

#pragma unroll
    for (int pass = 0; pass < NPASS; pass++) {
        const __half* Ap;
        const __half* Bp;
        int Kp;
        if (MODE == 0) {
            if (pass == 0) { Ap = d_xh; Bp = d_W1h; Kp = DIN; }
            else           { Ap = d_countsh; Bp = d_RW1h; Kp = RR; }
        } else {
            Ap = d_agg1h; Bp = d_W2h; Kp = W1COLS;
        }

        int gr = rowBase + fa_row;
        int aOK = (gr < M) ? 16 : 0;
        const __half* aSrc0 = Ap + (size_t)((gr < M) ? gr : (M - 1)) * Kp + fa_seg;
        const __half* bSrc0 = Bp + (size_t)fb_row * N + colBase + fb_seg;
        uint32_t aDst = (uint32_t)(fa_row * AROW + fa_seg) * 2;
        uint32_t bDst = (uint32_t)(fb_row * BROW + fb_seg) * 2;

        int nT = Kp / BK;

        cp_async16(aSm[0] + aDst, aSrc0, aOK);
        cp_async16(aSm[0] + aDst + 16, aSrc0 + 8, aOK);
        cp_async16(bSm[0] + bDst, bSrc0, 16);
        cp_async16(bSm[0] + bDst + 16, bSrc0 + 8, 16);
        cp_commit();

        for (int kt = 0; kt < nT; kt++) {
            if (kt + 1 < nT) {
                int buf = (kt + 1) & 1;
                int k0 = (kt + 1) * BK;
                cp_async16(aSm[buf] + aDst, aSrc0 + k0, aOK);
                cp_async16(aSm[buf] + aDst + 16, aSrc0 + k0 + 8, aOK);
                const __half* bs = bSrc0 + (size_t)k0 * N;
                cp_async16(bSm[buf] + bDst, bs, 16);
                cp_async16(bSm[buf] + bDst + 16, bs + 8, 16);
                cp_commit();
                cp_wait<1>();
            } else {
                cp_wait<0>();
            }
            __syncthreads();

            int buf = kt & 1;
#pragma unroll
            for (int kk = 0; kk < BK; kk += 16) {
                uint32_t a[4][4];
#pragma unroll
                for (int mi = 0; mi < 4; mi++) {
                    uint32_t addr = aSm[buf] +
                        (uint32_t)(((wm + mi * 16 + lrow) * AROW + kk + lcol8) * 2);
                    ldsm_x4(a[mi], addr);
                }
                uint32_t bt[2][4];
#pragma unroll
                for (int p = 0; p < 2; p++) {
                    uint32_t addr = bSm[buf] +
                        (uint32_t)(((kk + lrow) * BROW + wn + p * 16 + lcol8) * 2);
                    ldsm_x4_t(bt[p], addr);
                }
#pragma unroll
                for (int mi = 0; mi < 4; mi++)
#pragma unroll
                    for (int nj = 0; nj < 4; nj++) {
                        uint32_t b0 = bt[nj >> 1][(nj & 1) * 2];
                        uint32_t b1 = bt[nj >> 1][(nj & 1) * 2 + 1];
                        asm volatile(
                            "mma.sync.aligned.m16n8k16.row.col.f32.f16.f16.f32 "
                            "{%0,%1,%2,%3}, {%4,%5,%6,%7}, {%8,%9}, {%0,%1,%2,%3};"
                            : "+f"(acc[mi][nj][0]), "+f"(acc[mi][nj][1]),
                              "+f"(acc[mi][nj][2]), "+f"(acc[mi][nj][3])
                            : "r"(a[mi][0]), "r"(a[mi][1]), "r"(a[mi][2]), "r"(a[mi][3]),
                              "r"(b0), "r"(b1));
                    }
            }
            __syncthreads();
        }
    }

    __half* Ch = (MODE == 0) ? d_h1h : d_h2h;
#pragma unroll
    for (int mi = 0; mi < 4; mi++) {
#pragma unroll
        for (int nj = 0; nj < 4; nj++) {
            int row = rowBase + wm + mi * 16 + g;
            int col = colBase + wn + nj * 8 + tig * 2;
            if (row < M)
                *(__half2*)&Ch[(size_t)row * N + col] =
                    __floats2half2_rn(acc[mi][nj][0], acc[mi][nj][1]);
            if (row + 8 < M)
                *(__half2*)&Ch[(size_t)(row + 8) * N + col] =
                    __floats2half2_rn(acc[mi][nj][2], acc[mi][nj][3]);
        }
    }
}

// ---------------- attention dot products (fp16 features) ----------------
__global__ void k_attn1(const float* __restrict__ att_s, const float* __restrict__ att_d) {
    int n = blockIdx.x;
    int w = threadIdx.x / 32, l = threadIdx.x % 32;
    int offs = w * HID + l * 4;
    uint2 hv = *(const uint2*)&d_h1h[(size_t)n * W1COLS + offs];
    float2 f01 = __half22float2(*(__half2*)&hv.x);
    float2 f23 = __half22float2(*(__half2*)&hv.y);
    float4 s4 = *(const float4*)&att_s[offs];
    float4 dd4 = *(const float4*)&att_d[offs];
    float ss = f01.x * s4.x + f01.y * s4.y + f23.x * s4.z + f23.y * s4.w;
    float dd = f01.x * dd4.x + f01.y * dd4.y + f23.x * dd4.z + f23.y * dd4.w;
#pragma unroll
    for (int off = 16; off; off >>= 1) {
        ss += __shfl_down_sync(0xffffffffu, ss, off);
        dd += __shfl_down_sync(0xffffffffu, dd, off);
    }
    if (l == 0) { d_as1[n * HEADSN + w] = ss; d_ad1[n * HEADSN + w] = dd; }
}

__global__ void k_attn2(const float* __restrict__ att_s, const float* __restrict__ att_d) {
    int n = blockIdx.x;
    int l = threadIdx.x;   // 32
    int offs = l * 4;
    uint2 hv = *(const uint2*)&d_h2h[(size_t)n * DOUT + offs];
    float2 f01 = __half22float2(*(__half2*)&hv.x);
    float2 f23 = __half22float2(*(__half2*)&hv.y);
    float4 s4 = *(const float4*)&att_s[offs];
    float4 dd4 = *(const float4*)&att_d[offs];
    float ss = f01.x * s4.x + f01.y * s4.y + f23.x * s4.z + f23.y * s4.w;
    float dd = f01.x * dd4.x + f01.y * dd4.y + f23.x * dd4.z + f23.y * dd4.w;
#pragma unroll
    for (int off = 16; off; off >>= 1) {
        ss += __shfl_down_sync(0xffffffffu, ss, off);
        dd += __shfl_down_sync(0xffffffffu, dd, off);
    }
    if (l == 0) { d_as2[n] = ss; d_ad2[n] = dd; }
}

// ---------------- edge-parallel softmax weights ----------------
template <int LAYER>
__global__ void k_wt() {
    int e = blockIdx.x * blockDim.x + threadIdx.x;
    if (e >= E2) return;
    int2 sd = d_csr[e];
    if (LAYER == 0) {
        float4 as = *(const float4*)&d_as1[sd.x * HEADSN];
        float4 ad = *(const float4*)&d_ad1[sd.y * HEADSN];
        float ev0 = as.x + ad.x, ev1 = as.y + ad.y;
        float ev2 = as.z + ad.z, ev3 = as.w + ad.w;
        ev0 = ev0 > 0.f ? ev0 : 0.2f * ev0;
        ev1 = ev1 > 0.f ? ev1 : 0.2f * ev1;
        ev2 = ev2 > 0.f ? ev2 : 0.2f * ev2;
        ev3 = ev3 > 0.f ? ev3 : 0.2f * ev3;
        float4 w;
        w.x = __expf(ev0); w.y = __expf(ev1); w.z = __expf(ev2); w.w = __expf(ev3);
        *(float4*)&d_w1[(size_t)e * 4] = w;
    } else {
        float ev = d_as2[sd.x] + d_ad2[sd.y];
        ev = ev > 0.f ? ev : 0.2f * ev;
        d_w2[e] = __expf(ev);
    }
}

// ---------------- aggregation layer 1 (fp16 gathers; writes fp16) ----------
__global__ __launch_bounds__(128) void k_agg1(const float* __restrict__ bias) {
    int n = blockIdx.x;
    int t = threadIdx.x;
    int hh = t >> 5;
    int elt = t * 4;
    int beg = d_offsets[n], end = d_offsets[n + 1];

    float dA = 0.f, dB = 0.f;
    float a0 = 0.f, a1 = 0.f, a2 = 0.f, a3 = 0.f;
    float b0 = 0.f, b1 = 0.f, b2 = 0.f, b3 = 0.f;

    int e = beg;
    for (; e + 1 < end; e += 2) {
        int s0 = d_csr[e].x;
        int s1 = d_csr[e + 1].x;
        float4 wA = *(const float4*)&d_w1[(size_t)e * 4];
        float4 wB = *(const float4*)&d_w1[(size_t)(e + 1) * 4];
        float wa = (hh == 0) ? wA.x : (hh == 1) ? wA.y : (hh == 2) ? wA.z : wA.w;
        float wb = (hh == 0) ? wB.x : (hh == 1) ? wB.y : (hh == 2) ? wB.z : wB.w;
        uint2 pA = *(const uint2*)&d_h1h[(size_t)s0 * W1COLS + elt];
        uint2 pB = *(const uint2*)&d_h1h[(size_t)s1 * W1COLS + elt];
        float2 fA01 = __half22float2(*(__half2*)&pA.x), fA23 = __half22float2(*(__half2*)&pA.y);
        float2 fB01 = __half22float2(*(__half2*)&pB.x), fB23 = __half22float2(*(__half2*)&pB.y);
        dA += wa; dB += wb;
        a0 = fmaf(wa, fA01.x, a0); a1 = fmaf(wa, fA01.y, a1);
        a2 = fmaf(wa, fA23.x, a2); a3 = fmaf(wa, fA23.y, a3);
        b0 = fmaf(wb, fB01.x, b0); b1 = fmaf(wb, fB01.y, b1);
        b2 = fmaf(wb, fB23.x, b2); b3 = fmaf(wb, fB23.y, b3);
    }
    if (e < end) {
        int s0 = d_csr[e].x;
        float4 wA = *(const float4*)&d_w1[(size_t)e * 4];
        float wa = (hh == 0) ? wA.x : (hh == 1) ? wA.y : (hh == 2) ? wA.z : wA.w;
        uint2 pA = *(const uint2*)&d_h1h[(size_t)s0 * W1COLS + elt];
        float2 fA01 = __half22float2(*(__half2*)&pA.x), fA23 = __half22float2(*(__half2*)&pA.y);
        dA += wa;
        a0 = fmaf(wa, fA01.x, a0); a1 = fmaf(wa, fA01.y, a1);
        a2 = fmaf(wa, fA23.x, a2); a3 = fmaf(wa, fA23.y, a3);
    }

    float denom = dA + dB;
    float inv = 1.f / (denom + 1e-16f);
    float o0 = (a0 + b0) * inv + bias[elt + 0];
    float o1 = (a1 + b1) * inv + bias[elt + 1];
    float o2 = (a2 + b2) * inv + bias[elt + 2];
    float o3 = (a3 + b3) * inv + bias[elt + 3];
    o0 = o0 > 0.f ? o0 : expm1f(o0);
    o1 = o1 > 0.f ? o1 : expm1f(o1);
    o2 = o2 > 0.f ? o2 : expm1f(o2);
    o3 = o3 > 0.f ? o3 : expm1f(o3);
    __half2 p01 = __floats2half2_rn(o0, o1);
    __half2 p23 = __floats2half2_rn(o2, o3);
    uint2 pk;
    pk.x = *(uint32_t*)&p01;
    pk.y = *(uint32_t*)&p23;
    *(uint2*)&d_agg1h[(size_t)n * W1COLS + elt] = pk;
}

// ---------------- aggregation layer 2 (unroll x4) ----------------
__global__ __launch_bounds__(128) void k_agg2(const float* __restrict__ bias,
                                              float* __restrict__ out) {
    int n = blockIdx.x;
    int t = threadIdx.x;
    int beg = d_offsets[n], end = d_offsets[n + 1];

    float den0 = 0.f, den1 = 0.f, den2 = 0.f, den3 = 0.f;
    float ac0 = 0.f, ac1 = 0.f, ac2 = 0.f, ac3 = 0.f;

    int e = beg;
    for (; e + 3 < end; e += 4) {
        int s0 = d_csr[e].x, s1 = d_csr[e + 1].x;
        int s2 = d_csr[e + 2].x, s3 = d_csr[e + 3].x;
        float w0 = d_w2[e], w1 = d_w2[e + 1], w2 = d_w2[e + 2], w3 = d_w2[e + 3];
        float v0 = __half2float(d_h2h[(size_t)s0 * DOUT + t]);
        float v1 = __half2float(d_h2h[(size_t)s1 * DOUT + t]);
        float v2 = __half2float(d_h2h[(size_t)s2 * DOUT + t]);
        float v3 = __half2float(d_h2h[(size_t)s3 * DOUT + t]);
        den0 += w0; den1 += w1; den2 += w2; den3 += w3;
        ac0 = fmaf(w0, v0, ac0); ac1 = fmaf(w1, v1, ac1);
        ac2 = fmaf(w2, v2, ac2); ac3 = fmaf(w3, v3, ac3);
    }
    for (; e < end; e++) {
        int s0 = d_csr[e].x;
        float w0 = d_w2[e];
        float v0 = __half2float(d_h2h[(size_t)s0 * DOUT + t]);
        den0 += w0;
        ac0 = fmaf(w0, v0, ac0);
    }

    float denom = (den0 + den1) + (den2 + den3);
    float acc = (ac0 + ac1) + (ac2 + ac3);
    out[(size_t)n * DOUT + t] = acc / (denom + 1e-16f) + bias[t];
}

// ---------------- host side ----------------
extern "C" void kernel_launch(void* const* d_in, const int* in_sizes, int n_in,
                              void* d_out, int out_size) {
    const float* x    = (const float*)d_in[0];
    const int*   ei   = (const int*)d_in[1];
    const int*   et   = (const int*)d_in[2];
    const float* rel  = (const float*)d_in[3];
    const float* W1   = (const float*)d_in[4];
    const float* as1w = (const float*)d_in[5];
    const float* ad1w = (const float*)d_in[6];
    const float* b1   = (const float*)d_in[7];
    const float* W2   = (const float*)d_in[8];
    const float* as2w = (const float*)d_in[9];
    const float* ad2w = (const float*)d_in[10];
    const float* b2   = (const float*)d_in[11];
    float*       out  = (float*)d_out;

    // launch order keeps gemm0 in the ncu capture slot (4th launch)
    k_init<<<(NN * RR + 255) / 256, 256>>>();
    k_hist<<<(EE + 255) / 256, 256>>>(ei, et);
    k_prep<<<PREP_RW1 + PREP_X + PREP_CNT + PREP_W1 + PREP_W2, 512>>>(x, rel, W1, W2);

    {
        dim3 grid(W1COLS / 128, (NN + 127) / 128);
        k_gemm_tc<0><<<grid, 256>>>();               // <- capture slot
    }

    k_scan<<<1, 1024>>>();
    k_fill<<<(E2 + 255) / 256, 256>>>(ei);

    k_attn1<<<NN, 128>>>(as1w, ad1w);
    k_wt<0><<<(E2 + 255) / 256, 256>>>();
    k_agg1<<<NN, 128>>>(b1);

    {
        dim3 grid(DOUT / 128, (NN + 127) / 128);
        k_gemm_tc<1><<<grid, 256>>>();
    }
    k_attn2<<<NN, 32>>>(as2w, ad2w);
    k_wt<1><<<(E2 + 255) / 256, 256>>>();
    k_agg2<<<NN, 128>>>(b2, out);
}